// round 11
// baseline (speedup 1.0000x reference)
#include <cuda_runtime.h>
#include <cuda_fp16.h>
#include <math.h>
#include <stdint.h>

#define B_   2
#define T_   2048
#define H_   8
#define DK_  256
#define DV_  512
#define C_   64
#define NCH  32            // T_/C_
#define MR   (B_*T_)       // 4096 rows

typedef unsigned long long u64;

// ---------------- scratch (no allocations allowed) ----------------
__device__ float g_q[(size_t)MR*H_*DK_];   // [b,t,h,dk]
__device__ float g_k[(size_t)MR*H_*DK_];
__device__ float g_v[(size_t)MR*H_*DV_];   // [b,t,h,dv]
__device__ float g_g[(size_t)MR*H_*DV_];
__device__ float g_o[(size_t)MR*H_*DV_];
__device__ float g_rc[T_*128];
__device__ float g_rs[T_*128];

// fp16 operand buffers
__device__ __half g_hsh[(size_t)MR*2048];
__device__ __half g_wq[(size_t)2048*2048];
__device__ __half g_wk[(size_t)2048*2048];
__device__ __half g_wv[(size_t)4096*2048];
__device__ __half g_wg[(size_t)4096*2048];
__device__ __half g_wo[(size_t)2048*4096];
__device__ __half g_oh[(size_t)MR*4096], g_ol[(size_t)MR*4096];

// ================= PTX helpers =================
__device__ __forceinline__ uint32_t smem_u32(const void* p) {
    uint32_t a;
    asm("{ .reg .u64 t; cvta.to.shared.u64 t, %1; cvt.u32.u64 %0, t; }" : "=r"(a) : "l"(p));
    return a;
}
__device__ __forceinline__ void cpa16(uint32_t s, const void* g) {
    asm volatile("cp.async.cg.shared.global [%0], [%1], 16;" :: "r"(s), "l"(g));
}
__device__ __forceinline__ void cp_commit() {
    asm volatile("cp.async.commit_group;" ::: "memory");
}
__device__ __forceinline__ void cp_wait2() {
    asm volatile("cp.async.wait_group 2;" ::: "memory");
}
__device__ __forceinline__ void ldm4(uint32_t* r, uint32_t a) {
    asm volatile("ldmatrix.sync.aligned.m8n8.x4.shared.b16 {%0,%1,%2,%3}, [%4];"
        : "=r"(r[0]), "=r"(r[1]), "=r"(r[2]), "=r"(r[3]) : "r"(a));
}
__device__ __forceinline__ void mma16816(float* c, const uint32_t* a, const uint32_t* b) {
    asm volatile(
        "mma.sync.aligned.m16n8k16.row.col.f32.f16.f16.f32 "
        "{%0,%1,%2,%3}, {%4,%5,%6,%7}, {%8,%9}, {%0,%1,%2,%3};"
        : "+f"(c[0]), "+f"(c[1]), "+f"(c[2]), "+f"(c[3])
        : "r"(a[0]), "r"(a[1]), "r"(a[2]), "r"(a[3]), "r"(b[0]), "r"(b[1]));
}
// packed f32x2
__device__ __forceinline__ u64 pack2(float x, float y) {
    u64 r; asm("mov.b64 %0, {%1, %2};" : "=l"(r) : "f"(x), "f"(y)); return r;
}
__device__ __forceinline__ u64 bcast2(float x) { return pack2(x, x); }
#define FMA2(d, a, b) asm("fma.rn.f32x2 %0, %1, %2, %0;" : "+l"(d) : "l"(a), "l"(b))
__device__ __forceinline__ void unpack2(u64 v, float& lo, float& hi) {
    asm("mov.b64 {%0, %1}, %2;" : "=f"(lo), "=f"(hi) : "l"(v));
}
__device__ __forceinline__ float gpow(float lg2, float e) {
    return exp2f(e * lg2);
}

// ================= conversion kernels =================
__global__ void conv_f16(const float* __restrict__ x, __half* __restrict__ h, int n4)
{
    int i = blockIdx.x * 256 + threadIdx.x;
    if (i >= n4) return;
    float4 v = *(const float4*)(x + (size_t)i * 4);
    __half2 a = __floats2half2_rn(v.x, v.y);
    __half2 b = __floats2half2_rn(v.z, v.w);
    *(uint2*)(h + (size_t)i*4) = make_uint2(
        *(uint32_t*)&a, *(uint32_t*)&b);
}

// W[K,N] -> Wt fp16 [N,K]
__global__ void tconv(const float* __restrict__ W, __half* __restrict__ h, int K, int N)
{
    __shared__ float tile[32][33];
    int k0 = blockIdx.y * 32, n0 = blockIdx.x * 32;
    int tx = threadIdx.x, ty = threadIdx.y;
#pragma unroll
    for (int i = 0; i < 4; i++)
        tile[ty + 8*i][tx] = W[(size_t)(k0 + ty + 8*i) * N + n0 + tx];
    __syncthreads();
#pragma unroll
    for (int i = 0; i < 4; i++)
        h[(size_t)(n0 + ty + 8*i) * K + k0 + tx] = __float2half(tile[tx][ty + 8*i]);
}

// ================= HMMA GEMM: C[M,N] = (Ah[+Al])[M,K] @ Bt[N,K]^T =================
// fp16 operands, fp32 accum. CTA tile 128x128, BK=32, 4-stage cp.async.
#define OAH 0u
#define OAL 10240u
#define OBH 20480u
#define SSTG 30720u
#define GEMM_SMEM (4*30720)

template<bool TWO>
__global__ __launch_bounds__(256, 1) void gemm_mma(
    const __half* __restrict__ Ah, const __half* __restrict__ Al,
    const __half* __restrict__ Bh,
    float* __restrict__ Cc, int M, int N, int K)
{
    extern __shared__ __align__(128) char smc[];
    const uint32_t sb = smem_u32(smc);
    const int tid = threadIdx.x;
    const int lane = tid & 31, w = tid >> 5;
    const int wm = w & 3, wn = w >> 2;
    const int m0 = blockIdx.y * 128, n0 = blockIdx.x * 128;
    const int NC = K >> 5;

    float c[2][8][4] = {};

    auto load_stage = [&](int s, int k0) {
        uint32_t base = sb + (uint32_t)s * SSTG;
#pragma unroll
        for (int i = 0; i < 2; i++) {
            int idx = tid + (i << 8);
            int r = idx >> 2, kc = idx & 3;
            uint32_t da = base + r * 80 + kc * 16;
            size_t ga = (size_t)(m0 + r) * K + k0 + kc * 8;
            cpa16(da + OAH, Ah + ga);
            if (TWO) cpa16(da + OAL, Al + ga);
            size_t gb = (size_t)(n0 + r) * K + k0 + kc * 8;
            cpa16(da + OBH, Bh + gb);
        }
    };

    load_stage(0, 0);  cp_commit();
    load_stage(1, 32); cp_commit();
    load_stage(2, 64); cp_commit();

    for (int i = 0; i < NC; i++) {
        cp_wait2();
        __syncthreads();
        if (i + 3 < NC) load_stage((i + 3) & 3, (i + 3) << 5);
        cp_commit();

        uint32_t base = sb + (uint32_t)(i & 3) * SSTG;
#pragma unroll
        for (int ks = 0; ks < 2; ks++) {
            uint32_t ah[2][4], al[2][4];
#pragma unroll
            for (int mt = 0; mt < 2; mt++) {
                int row = wm * 32 + mt * 16 + (lane & 15);
                int kc = ks * 2 + (lane >> 4);
                uint32_t ad = base + row * 80 + kc * 16;
                ldm4(ah[mt], ad + OAH);
                if (TWO) ldm4(al[mt], ad + OAL);
            }
            uint32_t bh[4][4];
#pragma unroll
            for (int np = 0; np < 4; np++) {
                int row = wn * 64 + np * 16 + (lane & 7) + ((lane & 16) >> 1);
                int kc = ks * 2 + ((lane >> 3) & 1);
                uint32_t bd = base + row * 80 + kc * 16;
                ldm4(bh[np], bd + OBH);
            }
#pragma unroll
            for (int mt = 0; mt < 2; mt++)
#pragma unroll
                for (int np = 0; np < 4; np++)
#pragma unroll
                    for (int hf = 0; hf < 2; hf++) {
                        float* cc = c[mt][np * 2 + hf];
                        mma16816(cc, ah[mt], &bh[np][hf * 2]);
                        if (TWO) mma16816(cc, al[mt], &bh[np][hf * 2]);
                    }
        }
        __syncthreads();
    }

    const int rbase = m0 + wm * 32 + (lane >> 2);
    const int cbase = n0 + wn * 64 + (lane & 3) * 2;
#pragma unroll
    for (int mt = 0; mt < 2; mt++)
#pragma unroll
        for (int nt = 0; nt < 8; nt++) {
            *(float2*)&Cc[(size_t)(rbase + mt * 16) * N + cbase + nt * 8] =
                make_float2(c[mt][nt][0], c[mt][nt][1]);
            *(float2*)&Cc[(size_t)(rbase + mt * 16 + 8) * N + cbase + nt * 8] =
                make_float2(c[mt][nt][2], c[mt][nt][3]);
        }
}

// ---------------- rotary (fp32, mirrors the reference's own f32 math) --------
__global__ void rope_table(float* __restrict__ rc, float* __restrict__ rs)
{
    int idx = blockIdx.x * blockDim.x + threadIdx.x;   // t*128 + j
    if (idx >= T_*128) return;
    int t = idx >> 7, j = idx & 127;
    float inv = 1.0f / powf(10000.0f, (float)j * (1.0f/128.0f));
    float a = (float)t * inv;
    float s, c;
    sincosf(a, &s, &c);
    rc[idx] = c;
    rs[idx] = s;
}

__global__ void rope_apply(float* __restrict__ q, float* __restrict__ k,
                           const float* __restrict__ rc, const float* __restrict__ rs)
{
    int idx = blockIdx.x * blockDim.x + threadIdx.x;
    if (idx >= B_*T_*H_*128) return;
    int j = idx & 127;
    int h = (idx >> 7) & (H_-1);
    int t = (idx >> 10) & (T_-1);
    int b = idx >> 21;
    float c = rc[t*128 + j], s = rs[t*128 + j];
    size_t base = ((size_t)(b*T_ + t)*H_ + h)*DK_;
    float x1 = q[base + j], x2 = q[base + 128 + j];
    q[base + j]       = x1*c - x2*s;
    q[base + 128 + j] = x2*c + x1*s;
    x1 = k[base + j]; x2 = k[base + 128 + j];
    k[base + j]       = x1*c - x2*s;
    k[base + 128 + j] = x2*c + x1*s;
}

// ---------------- retention: intra-chunk (fully parallel) ----------------
__global__ __launch_bounds__(256) void ret_intra(
    const float* __restrict__ q, const float* __restrict__ k,
    const float* __restrict__ v, float* __restrict__ o)
{
    extern __shared__ float sm[];
    float* sQt = sm;              // [256][64]
    float* sKt = sm + 16384;      // [256][64]
    float* sA  = sm + 32768;      // [64][64]
    float* sV  = sm;              // reuse [64][512]
    __shared__ float gp[64];

    int bx = blockIdx.x;
    int n = bx % NCH; int h = (bx / NCH) % H_; int b = bx / (NCH*H_);
    int tid = threadIdx.x;
    float gamma = 1.f - exp2f(-5.f - (float)h);
    float lg2 = log2f(gamma);
    if (tid < 64) gp[tid] = gpow(lg2, (float)tid);

    const size_t qbase = ((size_t)(b*T_ + n*C_)*H_ + h)*DK_;
#pragma unroll
    for (int r = 0; r < 16; r++) {
        int idx = tid + 256*r;
        int row = idx >> 6;
        int d4  = (idx & 63) << 2;
        float4 qv = *(const float4*)(q + qbase + (size_t)row*H_*DK_ + d4);
        sQt[(d4+0)*64 + row] = qv.x * 0.0625f;
        sQt[(d4+1)*64 + row] = qv.y * 0.0625f;
        sQt[(d4+2)*64 + row] = qv.z * 0.0625f;
        sQt[(d4+3)*64 + row] = qv.w * 0.0625f;
        float4 kv = *(const float4*)(k + qbase + (size_t)row*H_*DK_ + d4);
        sKt[(d4+0)*64 + row] = kv.x;
        sKt[(d4+1)*64 + row] = kv.y;
        sKt[(d4+2)*64 + row] = kv.z;
        sKt[(d4+3)*64 + row] = kv.w;
    }
    __syncthreads();
    {
        int ti = tid >> 4, tj = tid & 15;
        u64 acc2[4][2] = {};
        for (int d = 0; d < 256; d++) {
            float4 qa = *(float4*)(sQt + d*64 + ti*4);
            ulonglong2 ka = *(ulonglong2*)(sKt + d*64 + tj*4);
            u64 q0 = bcast2(qa.x), q1 = bcast2(qa.y), q2 = bcast2(qa.z), q3 = bcast2(qa.w);
            FMA2(acc2[0][0], q0, ka.x); FMA2(acc2[0][1], q0, ka.y);
            FMA2(acc2[1][0], q1, ka.x); FMA2(acc2[1][1], q1, ka.y);
            FMA2(acc2[2][0], q2, ka.x); FMA2(acc2[2][1], q2, ka.y);
            FMA2(acc2[3][0], q3, ka.x); FMA2(acc2[3][1], q3, ka.y);
        }
#pragma unroll
        for (int a = 0; a < 4; a++) {
            float f[4];
            unpack2(acc2[a][0], f[0], f[1]);
            unpack2(acc2[a][1], f[2], f[3]);
#pragma unroll
            for (int c = 0; c < 4; c++) {
                int i = ti*4 + a, j = tj*4 + c;
                sA[i*64 + j] = (i >= j) ? f[c] * gp[i-j] : 0.f;
            }
        }
    }
    __syncthreads();
    const size_t vbase = ((size_t)(b*T_ + n*C_)*H_ + h)*DV_;
#pragma unroll
    for (int r = 0; r < 32; r++) {
        int idx = tid + 256*r;
        int row = idx >> 7;
        int v4  = (idx & 127) << 2;
        *(float4*)(sV + row*512 + v4) =
            *(const float4*)(v + vbase + (size_t)row*H_*DV_ + v4);
    }
    __syncthreads();
    int ty = tid >> 6;
    int tx = tid & 63;
    for (int ii = 0; ii < 16; ii++) {
        int i = ty*16 + ii;
        u64 acc2[4] = {};
        for (int j = 0; j < 64; j++) {
            u64 ab = bcast2(sA[i*64 + j]);
            ulonglong2 v0 = *(ulonglong2*)(sV + j*512 + tx*8);
            ulonglong2 v1 = *(ulonglong2*)(sV + j*512 + tx*8 + 4);
            FMA2(acc2[0], ab, v0.x); FMA2(acc2[1], ab, v0.y);
            FMA2(acc2[2], ab, v1.x); FMA2(acc2[3], ab, v1.y);
        }
        float* op = o + vbase + (size_t)i*H_*DV_ + tx*8;
        *(ulonglong2*)op       = make_ulonglong2(acc2[0], acc2[1]);
        *(ulonglong2*)(op + 4) = make_ulonglong2(acc2[2], acc2[3]);
    }
}

// ---------------- retention: inter-chunk scan ----------------
__global__ __launch_bounds__(256) void ret_inter(
    const float* __restrict__ q, const float* __restrict__ k,
    const float* __restrict__ v, float* __restrict__ o)
{
    extern __shared__ float sm[];
    float* S   = sm;
    float* sQt = sm + 16384;
    float* sK  = sm + 32768;
    float* sV  = sm + 49152;
    __shared__ float qdv[64], kdv[64];

    int bx = blockIdx.x;
    int vs = bx & 7; int h = (bx >> 3) & 7; int b = bx >> 6;
    int v0 = vs * 64;
    int tid = threadIdx.x;
    float gamma = 1.f - exp2f(-5.f - (float)h);
    float lg2 = log2f(gamma);
    if (tid < 64) {
        qdv[tid] = 0.0625f * gpow(lg2, (float)(tid + 1));
        kdv[tid] = gpow(lg2, (float)(63 - tid));
    }
    float gC = gpow(lg2, 64.f);
    u64 gC2 = bcast2(gC);
#pragma unroll
    for (int r = 0; r < 64; r++) S[tid + 256*r] = 0.f;
    __syncthreads();

    for (int n = 0; n < NCH; n++) {
        const size_t qbase = ((size_t)(b*T_ + n*C_)*H_ + h)*DK_;
        const size_t vbase = ((size_t)(b*T_ + n*C_)*H_ + h)*DV_ + v0;
#pragma unroll
        for (int r = 0; r < 16; r++) {
            int idx = tid + 256*r;
            int row = idx >> 6;
            int d4  = (idx & 63) << 2;
            float4 qv = *(const float4*)(q + qbase + (size_t)row*H_*DK_ + d4);
            float qs = qdv[row];
            sQt[(d4+0)*64 + row] = qv.x*qs;
            sQt[(d4+1)*64 + row] = qv.y*qs;
            sQt[(d4+2)*64 + row] = qv.z*qs;
            sQt[(d4+3)*64 + row] = qv.w*qs;
            float4 kv = *(const float4*)(k + qbase + (size_t)row*H_*DK_ + d4);
            float ks = kdv[row];
            *(float4*)(sK + row*256 + d4) =
                make_float4(kv.x*ks, kv.y*ks, kv.z*ks, kv.w*ks);
        }
#pragma unroll
        for (int r = 0; r < 4; r++) {
            int idx = tid + 256*r;
            int row = idx >> 4;
            int v4  = (idx & 15) << 2;
            *(float4*)(sV + row*64 + v4) =
                *(const float4*)(v + vbase + (size_t)row*H_*DV_ + v4);
        }
        __syncthreads();

        if (n > 0) {    // o_inter = (Q*qd) @ S
            int ti = tid >> 4, tv = tid & 15;
            int i0 = ti*4, w0 = tv*4;
            u64 acc2[4][2] = {};
            for (int d = 0; d < 256; d++) {
                float4 qa = *(float4*)(sQt + d*64 + i0);
                ulonglong2 sa = *(ulonglong2*)(S + d*64 + w0);
                u64 q0 = bcast2(qa.x), q1 = bcast2(qa.y), q2 = bcast2(qa.z), q3 = bcast2(qa.w);
                FMA2(acc2[0][0], q0, sa.x); FMA2(acc2[0][1], q0, sa.y);
                FMA2(acc2[1][0], q1, sa.x); FMA2(acc2[1][1], q1, sa.y);
                FMA2(acc2[2][0], q2, sa.x); FMA2(acc2[2][1], q2, sa.y);
                FMA2(acc2[3][0], q3, sa.x); FMA2(acc2[3][1], q3, sa.y);
            }
#pragma unroll
            for (int a = 0; a < 4; a++) {
                float f[4];
                unpack2(acc2[a][0], f[0], f[1]);
                unpack2(acc2[a][1], f[2], f[3]);
                float* op = o + ((size_t)(b*T_ + n*C_ + i0 + a)*H_ + h)*DV_ + v0 + w0;
                float4 cur = *(float4*)op;
                cur.x += f[0]; cur.y += f[1]; cur.z += f[2]; cur.w += f[3];
                *(float4*)op = cur;
            }
        }
        __syncthreads();   // all S reads done before update

        {   // S = gC*S + (K*kd)^T @ V
            int td = tid >> 3, tw = tid & 7;
            int d0 = td*8, w0 = tw*8;
            u64 acc2[8][4] = {};
            for (int j = 0; j < 64; j++) {
                float ka[8];
                *(float4*)&ka[0] = *(float4*)(sK + j*256 + d0);
                *(float4*)&ka[4] = *(float4*)(sK + j*256 + d0 + 4);
                ulonglong2 va0 = *(ulonglong2*)(sV + j*64 + w0);
                ulonglong2 va1 = *(ulonglong2*)(sV + j*64 + w0 + 4);
#pragma unroll
                for (int a = 0; a < 8; a++) {
                    u64 kb = bcast2(ka[a]);
                    FMA2(acc2[a][0], kb, va0.x);
                    FMA2(acc2[a][1], kb, va0.y);
                    FMA2(acc2[a][2], kb, va1.x);
                    FMA2(acc2[a][3], kb, va1.y);
                }
            }
#pragma unroll
            for (int a = 0; a < 8; a++)
#pragma unroll
                for (int c2 = 0; c2 < 4; c2++) {
                    u64* sp = (u64*)(S + (d0+a)*64 + w0 + c2*2);
                    u64 sv = *sp;
                    FMA2(acc2[a][c2], gC2, sv);   // acc = gC*S + acc
                    *sp = acc2[a][c2];
                }
        }
        __syncthreads();
    }
}

// ---------------- RMSNorm + swish gate -> fp16 hi/lo ----------------
__global__ __launch_bounds__(128) void norm_gate(
    const float* __restrict__ o, const float* __restrict__ g, const float* __restrict__ w,
    __half* __restrict__ oh, __half* __restrict__ ol)
{
    int row = blockIdx.x;
    size_t base = (size_t)row * DV_;
    int tid = threadIdx.x;
    float x[4];
    *(float4*)x = *(const float4*)(o + base + tid*4);
    float ss = x[0]*x[0] + x[1]*x[1] + x[2]*x[2] + x[3]*x[3];
#pragma unroll
    for (int off = 16; off; off >>= 1) ss += __shfl_xor_sync(0xffffffffu, ss, off);
    __shared__ float ws[4];
    if ((tid & 31) == 0) ws[tid >> 5] = ss;
    __syncthreads();
    float tot = ws[0] + ws[1] + ws[2] + ws[3];
    float scale = rsqrtf(tot * (1.f/512.f) + 1e-5f);
    float gv[4], wv[4];
    *(float4*)gv = *(const float4*)(g + base + tid*4);
    *(float4*)wv = *(const float4*)(w + tid*4);
#pragma unroll
    for (int u = 0; u < 4; u++) {
        float sg = gv[u] / (1.f + expf(-gv[u]));
        float r = x[u] * scale * wv[u] * sg;
        __half hi = __float2half(r);
        oh[base + tid*4 + u] = hi;
        ol[base + tid*4 + u] = __float2half(r - __half2float(hi));
    }
}

// ---------------- launch ----------------
extern "C" void kernel_launch(void* const* d_in, const int* in_sizes, int n_in,
                              void* d_out, int out_size)
{
    const float* hs = (const float*)d_in[0];
    const float* Wq = (const float*)d_in[1];
    const float* Wk = (const float*)d_in[2];
    const float* Wv = (const float*)d_in[3];
    const float* Wg = (const float*)d_in[4];
    const float* Wo = (const float*)d_in[5];
    const float* gw = (const float*)d_in[6];
    float* out = (float*)d_out;

    float *q, *k, *v, *g, *o, *rc, *rs;
    cudaGetSymbolAddress((void**)&q,  g_q);
    cudaGetSymbolAddress((void**)&k,  g_k);
    cudaGetSymbolAddress((void**)&v,  g_v);
    cudaGetSymbolAddress((void**)&g,  g_g);
    cudaGetSymbolAddress((void**)&o,  g_o);
    cudaGetSymbolAddress((void**)&rc, g_rc);
    cudaGetSymbolAddress((void**)&rs, g_rs);

    __half *hsh, *wq, *wk, *wv, *wg, *wo, *oh, *ol;
    cudaGetSymbolAddress((void**)&hsh, g_hsh);
    cudaGetSymbolAddress((void**)&wq, g_wq);
    cudaGetSymbolAddress((void**)&wk, g_wk);
    cudaGetSymbolAddress((void**)&wv, g_wv);
    cudaGetSymbolAddress((void**)&wg, g_wg);
    cudaGetSymbolAddress((void**)&wo, g_wo);
    cudaGetSymbolAddress((void**)&oh, g_oh);  cudaGetSymbolAddress((void**)&ol, g_ol);

    cudaFuncSetAttribute(ret_intra, cudaFuncAttributeMaxDynamicSharedMemorySize, 147456);
    cudaFuncSetAttribute(ret_inter, cudaFuncAttributeMaxDynamicSharedMemorySize, 212992);
    cudaFuncSetAttribute(gemm_mma<true>,  cudaFuncAttributeMaxDynamicSharedMemorySize, GEMM_SMEM);
    cudaFuncSetAttribute(gemm_mma<false>, cudaFuncAttributeMaxDynamicSharedMemorySize, GEMM_SMEM);

    dim3 tb(32, 8);
    // 4 launches before the first GEMM -> ncu -s 5 -c 1 lands on gemm Q or K
    conv_f16<<<(MR*2048/4 + 255)/256, 256>>>(hs, hsh, MR*2048/4);
    tconv<<<dim3(64, 64),  tb>>>(Wq, wq, 2048, 2048);
    tconv<<<dim3(64, 64),  tb>>>(Wk, wk, 2048, 2048);
    tconv<<<dim3(128, 64), tb>>>(Wv, wv, 2048, 4096);

    // all input projections 1-term fp16
    gemm_mma<false><<<dim3(16, 32), 256, GEMM_SMEM>>>(hsh, hsh, wq, q, MR, 2048, 2048);
    gemm_mma<false><<<dim3(16, 32), 256, GEMM_SMEM>>>(hsh, hsh, wk, k, MR, 2048, 2048);
    gemm_mma<false><<<dim3(32, 32), 256, GEMM_SMEM>>>(hsh, hsh, wv, v, MR, 4096, 2048);

    tconv<<<dim3(128, 64), tb>>>(Wg, wg, 2048, 4096);
    gemm_mma<false><<<dim3(32, 32), 256, GEMM_SMEM>>>(hsh, hsh, wg, g, MR, 4096, 2048);
    tconv<<<dim3(64, 128), tb>>>(Wo, wo, 4096, 2048);

    rope_table<<<1024, 256>>>(rc, rs);
    rope_apply<<<(B_*T_*H_*128)/256, 256>>>(q, k, rc, rs);

    ret_intra<<<B_*H_*NCH, 256, 147456>>>(q, k, v, o);
    ret_inter<<<B_*H_*8,   256, 212992>>>(q, k, v, o);

    norm_gate<<<MR*H_, 128>>>(o, g, gw, oh, ol);

    // output projection stays 2-term (error passes straight to output)
    gemm_mma<true><<<dim3(16, 32), 256, GEMM_SMEM>>>(oh, ol, wo, out, MR, 2048, 4096);
}

// round 12
// speedup vs baseline: 1.5694x; 1.5694x over previous
#include <cuda_runtime.h>
#include <cuda_fp16.h>
#include <math.h>
#include <stdint.h>

#define B_   2
#define T_   2048
#define H_   8
#define DK_  256
#define DV_  512
#define C_   64
#define NCH  32            // T_/C_
#define MR   (B_*T_)       // 4096 rows

typedef unsigned long long u64;

// ---------------- scratch (no allocations allowed) ----------------
__device__ float g_q[(size_t)MR*H_*DK_];   // [b,t,h,dk]
__device__ float g_k[(size_t)MR*H_*DK_];
__device__ float g_v[(size_t)MR*H_*DV_];   // [b,t,h,dv]
__device__ float g_g[(size_t)MR*H_*DV_];
__device__ float g_o[(size_t)MR*H_*DV_];
__device__ float g_rc[T_*128];
__device__ float g_rs[T_*128];

// fp16 operand buffers
__device__ __half g_hsh[(size_t)MR*2048];
__device__ __half g_wq[(size_t)2048*2048];
__device__ __half g_wk[(size_t)2048*2048];
__device__ __half g_wv[(size_t)4096*2048];
__device__ __half g_wg[(size_t)4096*2048];
__device__ __half g_wo[(size_t)2048*4096];
__device__ __half g_oh[(size_t)MR*4096], g_ol[(size_t)MR*4096];

// ================= PTX helpers =================
__device__ __forceinline__ uint32_t smem_u32(const void* p) {
    uint32_t a;
    asm("{ .reg .u64 t; cvta.to.shared.u64 t, %1; cvt.u32.u64 %0, t; }" : "=r"(a) : "l"(p));
    return a;
}
__device__ __forceinline__ void cpa16(uint32_t s, const void* g) {
    asm volatile("cp.async.cg.shared.global [%0], [%1], 16;" :: "r"(s), "l"(g));
}
__device__ __forceinline__ void cp_commit() {
    asm volatile("cp.async.commit_group;" ::: "memory");
}
__device__ __forceinline__ void cp_wait2() {
    asm volatile("cp.async.wait_group 2;" ::: "memory");
}
__device__ __forceinline__ void ldm4(uint32_t* r, uint32_t a) {
    asm volatile("ldmatrix.sync.aligned.m8n8.x4.shared.b16 {%0,%1,%2,%3}, [%4];"
        : "=r"(r[0]), "=r"(r[1]), "=r"(r[2]), "=r"(r[3]) : "r"(a));
}
__device__ __forceinline__ void mma16816(float* c, const uint32_t* a, const uint32_t* b) {
    asm volatile(
        "mma.sync.aligned.m16n8k16.row.col.f32.f16.f16.f32 "
        "{%0,%1,%2,%3}, {%4,%5,%6,%7}, {%8,%9}, {%0,%1,%2,%3};"
        : "+f"(c[0]), "+f"(c[1]), "+f"(c[2]), "+f"(c[3])
        : "r"(a[0]), "r"(a[1]), "r"(a[2]), "r"(a[3]), "r"(b[0]), "r"(b[1]));
}
// packed f32x2
__device__ __forceinline__ u64 pack2(float x, float y) {
    u64 r; asm("mov.b64 %0, {%1, %2};" : "=l"(r) : "f"(x), "f"(y)); return r;
}
__device__ __forceinline__ u64 bcast2(float x) { return pack2(x, x); }
#define FMA2(d, a, b) asm("fma.rn.f32x2 %0, %1, %2, %0;" : "+l"(d) : "l"(a), "l"(b))
__device__ __forceinline__ void unpack2(u64 v, float& lo, float& hi) {
    asm("mov.b64 {%0, %1}, %2;" : "=f"(lo), "=f"(hi) : "l"(v));
}
__device__ __forceinline__ float gpow(float lg2, float e) {
    return exp2f(e * lg2);
}

// ================= conversion kernels =================
__global__ void conv_f16(const float* __restrict__ x, __half* __restrict__ h, int n4)
{
    int i = blockIdx.x * 256 + threadIdx.x;
    if (i >= n4) return;
    float4 v = *(const float4*)(x + (size_t)i * 4);
    __half2 a = __floats2half2_rn(v.x, v.y);
    __half2 b = __floats2half2_rn(v.z, v.w);
    *(uint2*)(h + (size_t)i*4) = make_uint2(
        *(uint32_t*)&a, *(uint32_t*)&b);
}

// W[K,N] -> Wt fp16 [N,K]
__global__ void tconv(const float* __restrict__ W, __half* __restrict__ h, int K, int N)
{
    __shared__ float tile[32][33];
    int k0 = blockIdx.y * 32, n0 = blockIdx.x * 32;
    int tx = threadIdx.x, ty = threadIdx.y;
#pragma unroll
    for (int i = 0; i < 4; i++)
        tile[ty + 8*i][tx] = W[(size_t)(k0 + ty + 8*i) * N + n0 + tx];
    __syncthreads();
#pragma unroll
    for (int i = 0; i < 4; i++)
        h[(size_t)(n0 + ty + 8*i) * K + k0 + tx] = __float2half(tile[tx][ty + 8*i]);
}

// ================= HMMA GEMM: C[M,N] = (Ah[+Al])[M,K] @ Bt[N,K]^T =================
// fp16 operands, fp32 accum. CTA tile 128x128, BK=32, 4-stage cp.async.
#define OAH 0u
#define OAL 10240u
#define OBH 20480u
#define SSTG 30720u
#define GEMM_SMEM (4*30720)

template<bool TWO>
__global__ __launch_bounds__(256, 1) void gemm_mma(
    const __half* __restrict__ Ah, const __half* __restrict__ Al,
    const __half* __restrict__ Bh,
    float* __restrict__ Cc, int M, int N, int K)
{
    extern __shared__ __align__(128) char smc[];
    const uint32_t sb = smem_u32(smc);
    const int tid = threadIdx.x;
    const int lane = tid & 31, w = tid >> 5;
    const int wm = w & 3, wn = w >> 2;
    const int m0 = blockIdx.y * 128, n0 = blockIdx.x * 128;
    const int NC = K >> 5;

    float c[2][8][4] = {};

    auto load_stage = [&](int s, int k0) {
        uint32_t base = sb + (uint32_t)s * SSTG;
#pragma unroll
        for (int i = 0; i < 2; i++) {
            int idx = tid + (i << 8);
            int r = idx >> 2, kc = idx & 3;
            uint32_t da = base + r * 80 + kc * 16;
            size_t ga = (size_t)(m0 + r) * K + k0 + kc * 8;
            cpa16(da + OAH, Ah + ga);
            if (TWO) cpa16(da + OAL, Al + ga);
            size_t gb = (size_t)(n0 + r) * K + k0 + kc * 8;
            cpa16(da + OBH, Bh + gb);
        }
    };

    load_stage(0, 0);  cp_commit();
    load_stage(1, 32); cp_commit();
    load_stage(2, 64); cp_commit();

    for (int i = 0; i < NC; i++) {
        cp_wait2();
        __syncthreads();
        if (i + 3 < NC) load_stage((i + 3) & 3, (i + 3) << 5);
        cp_commit();

        uint32_t base = sb + (uint32_t)(i & 3) * SSTG;
#pragma unroll
        for (int ks = 0; ks < 2; ks++) {
            uint32_t ah[2][4], al[2][4];
#pragma unroll
            for (int mt = 0; mt < 2; mt++) {
                int row = wm * 32 + mt * 16 + (lane & 15);
                int kc = ks * 2 + (lane >> 4);
                uint32_t ad = base + row * 80 + kc * 16;
                ldm4(ah[mt], ad + OAH);
                if (TWO) ldm4(al[mt], ad + OAL);
            }
            uint32_t bh[4][4];
#pragma unroll
            for (int np = 0; np < 4; np++) {
                int row = wn * 64 + np * 16 + (lane & 7) + ((lane & 16) >> 1);
                int kc = ks * 2 + ((lane >> 3) & 1);
                uint32_t bd = base + row * 80 + kc * 16;
                ldm4(bh[np], bd + OBH);
            }
#pragma unroll
            for (int mt = 0; mt < 2; mt++)
#pragma unroll
                for (int np = 0; np < 4; np++)
#pragma unroll
                    for (int hf = 0; hf < 2; hf++) {
                        float* cc = c[mt][np * 2 + hf];
                        mma16816(cc, ah[mt], &bh[np][hf * 2]);
                        if (TWO) mma16816(cc, al[mt], &bh[np][hf * 2]);
                    }
        }
        __syncthreads();
    }

    const int rbase = m0 + wm * 32 + (lane >> 2);
    const int cbase = n0 + wn * 64 + (lane & 3) * 2;
#pragma unroll
    for (int mt = 0; mt < 2; mt++)
#pragma unroll
        for (int nt = 0; nt < 8; nt++) {
            *(float2*)&Cc[(size_t)(rbase + mt * 16) * N + cbase + nt * 8] =
                make_float2(c[mt][nt][0], c[mt][nt][1]);
            *(float2*)&Cc[(size_t)(rbase + mt * 16 + 8) * N + cbase + nt * 8] =
                make_float2(c[mt][nt][2], c[mt][nt][3]);
        }
}

// ---------------- rotary (fp32, mirrors the reference's own f32 math) --------
__global__ void rope_table(float* __restrict__ rc, float* __restrict__ rs)
{
    int idx = blockIdx.x * blockDim.x + threadIdx.x;   // t*128 + j
    if (idx >= T_*128) return;
    int t = idx >> 7, j = idx & 127;
    float inv = 1.0f / powf(10000.0f, (float)j * (1.0f/128.0f));
    float a = (float)t * inv;
    float s, c;
    sincosf(a, &s, &c);
    rc[idx] = c;
    rs[idx] = s;
}

__global__ void rope_apply(float* __restrict__ q, float* __restrict__ k,
                           const float* __restrict__ rc, const float* __restrict__ rs)
{
    int idx = blockIdx.x * blockDim.x + threadIdx.x;
    if (idx >= B_*T_*H_*128) return;
    int j = idx & 127;
    int h = (idx >> 7) & (H_-1);
    int t = (idx >> 10) & (T_-1);
    int b = idx >> 21;
    float c = rc[t*128 + j], s = rs[t*128 + j];
    size_t base = ((size_t)(b*T_ + t)*H_ + h)*DK_;
    float x1 = q[base + j], x2 = q[base + 128 + j];
    q[base + j]       = x1*c - x2*s;
    q[base + 128 + j] = x2*c + x1*s;
    x1 = k[base + j]; x2 = k[base + 128 + j];
    k[base + j]       = x1*c - x2*s;
    k[base + 128 + j] = x2*c + x1*s;
}

// ---------------- retention: intra-chunk (fully parallel) ----------------
__global__ __launch_bounds__(256) void ret_intra(
    const float* __restrict__ q, const float* __restrict__ k,
    const float* __restrict__ v, float* __restrict__ o)
{
    extern __shared__ float sm[];
    float* sQt = sm;              // [256][64]
    float* sKt = sm + 16384;      // [256][64]
    float* sA  = sm + 32768;      // [64][64]
    float* sV  = sm;              // reuse [64][512]
    __shared__ float gp[64];

    int bx = blockIdx.x;
    int n = bx % NCH; int h = (bx / NCH) % H_; int b = bx / (NCH*H_);
    int tid = threadIdx.x;
    float gamma = 1.f - exp2f(-5.f - (float)h);
    float lg2 = log2f(gamma);
    if (tid < 64) gp[tid] = gpow(lg2, (float)tid);

    const size_t qbase = ((size_t)(b*T_ + n*C_)*H_ + h)*DK_;
#pragma unroll
    for (int r = 0; r < 16; r++) {
        int idx = tid + 256*r;
        int row = idx >> 6;
        int d4  = (idx & 63) << 2;
        float4 qv = *(const float4*)(q + qbase + (size_t)row*H_*DK_ + d4);
        sQt[(d4+0)*64 + row] = qv.x * 0.0625f;
        sQt[(d4+1)*64 + row] = qv.y * 0.0625f;
        sQt[(d4+2)*64 + row] = qv.z * 0.0625f;
        sQt[(d4+3)*64 + row] = qv.w * 0.0625f;
        float4 kv = *(const float4*)(k + qbase + (size_t)row*H_*DK_ + d4);
        sKt[(d4+0)*64 + row] = kv.x;
        sKt[(d4+1)*64 + row] = kv.y;
        sKt[(d4+2)*64 + row] = kv.z;
        sKt[(d4+3)*64 + row] = kv.w;
    }
    __syncthreads();
    {
        int ti = tid >> 4, tj = tid & 15;
        u64 acc2[4][2] = {};
        for (int d = 0; d < 256; d++) {
            float4 qa = *(float4*)(sQt + d*64 + ti*4);
            ulonglong2 ka = *(ulonglong2*)(sKt + d*64 + tj*4);
            u64 q0 = bcast2(qa.x), q1 = bcast2(qa.y), q2 = bcast2(qa.z), q3 = bcast2(qa.w);
            FMA2(acc2[0][0], q0, ka.x); FMA2(acc2[0][1], q0, ka.y);
            FMA2(acc2[1][0], q1, ka.x); FMA2(acc2[1][1], q1, ka.y);
            FMA2(acc2[2][0], q2, ka.x); FMA2(acc2[2][1], q2, ka.y);
            FMA2(acc2[3][0], q3, ka.x); FMA2(acc2[3][1], q3, ka.y);
        }
#pragma unroll
        for (int a = 0; a < 4; a++) {
            float f[4];
            unpack2(acc2[a][0], f[0], f[1]);
            unpack2(acc2[a][1], f[2], f[3]);
#pragma unroll
            for (int c = 0; c < 4; c++) {
                int i = ti*4 + a, j = tj*4 + c;
                sA[i*64 + j] = (i >= j) ? f[c] * gp[i-j] : 0.f;
            }
        }
    }
    __syncthreads();
    const size_t vbase = ((size_t)(b*T_ + n*C_)*H_ + h)*DV_;
#pragma unroll
    for (int r = 0; r < 32; r++) {
        int idx = tid + 256*r;
        int row = idx >> 7;
        int v4  = (idx & 127) << 2;
        *(float4*)(sV + row*512 + v4) =
            *(const float4*)(v + vbase + (size_t)row*H_*DV_ + v4);
    }
    __syncthreads();
    int ty = tid >> 6;
    int tx = tid & 63;
    for (int ii = 0; ii < 16; ii++) {
        int i = ty*16 + ii;
        u64 acc2[4] = {};
        for (int j = 0; j < 64; j++) {
            u64 ab = bcast2(sA[i*64 + j]);
            ulonglong2 v0 = *(ulonglong2*)(sV + j*512 + tx*8);
            ulonglong2 v1 = *(ulonglong2*)(sV + j*512 + tx*8 + 4);
            FMA2(acc2[0], ab, v0.x); FMA2(acc2[1], ab, v0.y);
            FMA2(acc2[2], ab, v1.x); FMA2(acc2[3], ab, v1.y);
        }
        float* op = o + vbase + (size_t)i*H_*DV_ + tx*8;
        *(ulonglong2*)op       = make_ulonglong2(acc2[0], acc2[1]);
        *(ulonglong2*)(op + 4) = make_ulonglong2(acc2[2], acc2[3]);
    }
}

// ---------------- retention: inter-chunk scan ----------------
__global__ __launch_bounds__(256) void ret_inter(
    const float* __restrict__ q, const float* __restrict__ k,
    const float* __restrict__ v, float* __restrict__ o)
{
    extern __shared__ float sm[];
    float* S   = sm;
    float* sQt = sm + 16384;
    float* sK  = sm + 32768;
    float* sV  = sm + 49152;
    __shared__ float qdv[64], kdv[64];

    int bx = blockIdx.x;
    int vs = bx & 7; int h = (bx >> 3) & 7; int b = bx >> 6;
    int v0 = vs * 64;
    int tid = threadIdx.x;
    float gamma = 1.f - exp2f(-5.f - (float)h);
    float lg2 = log2f(gamma);
    if (tid < 64) {
        qdv[tid] = 0.0625f * gpow(lg2, (float)(tid + 1));
        kdv[tid] = gpow(lg2, (float)(63 - tid));
    }
    float gC = gpow(lg2, 64.f);
    u64 gC2 = bcast2(gC);
#pragma unroll
    for (int r = 0; r < 64; r++) S[tid + 256*r] = 0.f;
    __syncthreads();

    for (int n = 0; n < NCH; n++) {
        const size_t qbase = ((size_t)(b*T_ + n*C_)*H_ + h)*DK_;
        const size_t vbase = ((size_t)(b*T_ + n*C_)*H_ + h)*DV_ + v0;
#pragma unroll
        for (int r = 0; r < 16; r++) {
            int idx = tid + 256*r;
            int row = idx >> 6;
            int d4  = (idx & 63) << 2;
            float4 qv = *(const float4*)(q + qbase + (size_t)row*H_*DK_ + d4);
            float qs = qdv[row];
            sQt[(d4+0)*64 + row] = qv.x*qs;
            sQt[(d4+1)*64 + row] = qv.y*qs;
            sQt[(d4+2)*64 + row] = qv.z*qs;
            sQt[(d4+3)*64 + row] = qv.w*qs;
            float4 kv = *(const float4*)(k + qbase + (size_t)row*H_*DK_ + d4);
            float ks = kdv[row];
            *(float4*)(sK + row*256 + d4) =
                make_float4(kv.x*ks, kv.y*ks, kv.z*ks, kv.w*ks);
        }
#pragma unroll
        for (int r = 0; r < 4; r++) {
            int idx = tid + 256*r;
            int row = idx >> 4;
            int v4  = (idx & 15) << 2;
            *(float4*)(sV + row*64 + v4) =
                *(const float4*)(v + vbase + (size_t)row*H_*DV_ + v4);
        }
        __syncthreads();

        if (n > 0) {    // o_inter = (Q*qd) @ S
            int ti = tid >> 4, tv = tid & 15;
            int i0 = ti*4, w0 = tv*4;
            u64 acc2[4][2] = {};
            for (int d = 0; d < 256; d++) {
                float4 qa = *(float4*)(sQt + d*64 + i0);
                ulonglong2 sa = *(ulonglong2*)(S + d*64 + w0);
                u64 q0 = bcast2(qa.x), q1 = bcast2(qa.y), q2 = bcast2(qa.z), q3 = bcast2(qa.w);
                FMA2(acc2[0][0], q0, sa.x); FMA2(acc2[0][1], q0, sa.y);
                FMA2(acc2[1][0], q1, sa.x); FMA2(acc2[1][1], q1, sa.y);
                FMA2(acc2[2][0], q2, sa.x); FMA2(acc2[2][1], q2, sa.y);
                FMA2(acc2[3][0], q3, sa.x); FMA2(acc2[3][1], q3, sa.y);
            }
#pragma unroll
            for (int a = 0; a < 4; a++) {
                float f[4];
                unpack2(acc2[a][0], f[0], f[1]);
                unpack2(acc2[a][1], f[2], f[3]);
                float* op = o + ((size_t)(b*T_ + n*C_ + i0 + a)*H_ + h)*DV_ + v0 + w0;
                float4 cur = *(float4*)op;
                cur.x += f[0]; cur.y += f[1]; cur.z += f[2]; cur.w += f[3];
                *(float4*)op = cur;
            }
        }
        __syncthreads();   // all S reads done before update

        {   // S = gC*S + (K*kd)^T @ V
            int td = tid >> 3, tw = tid & 7;
            int d0 = td*8, w0 = tw*8;
            u64 acc2[8][4] = {};
            for (int j = 0; j < 64; j++) {
                float ka[8];
                *(float4*)&ka[0] = *(float4*)(sK + j*256 + d0);
                *(float4*)&ka[4] = *(float4*)(sK + j*256 + d0 + 4);
                ulonglong2 va0 = *(ulonglong2*)(sV + j*64 + w0);
                ulonglong2 va1 = *(ulonglong2*)(sV + j*64 + w0 + 4);
#pragma unroll
                for (int a = 0; a < 8; a++) {
                    u64 kb = bcast2(ka[a]);
                    FMA2(acc2[a][0], kb, va0.x);
                    FMA2(acc2[a][1], kb, va0.y);
                    FMA2(acc2[a][2], kb, va1.x);
                    FMA2(acc2[a][3], kb, va1.y);
                }
            }
#pragma unroll
            for (int a = 0; a < 8; a++)
#pragma unroll
                for (int c2 = 0; c2 < 4; c2++) {
                    u64* sp = (u64*)(S + (d0+a)*64 + w0 + c2*2);
                    u64 sv = *sp;
                    FMA2(acc2[a][c2], gC2, sv);   // acc = gC*S + acc
                    *sp = acc2[a][c2];
                }
        }
        __syncthreads();
    }
}

// ---------------- RMSNorm + swish gate -> fp16 hi/lo ----------------
__global__ __launch_bounds__(128) void norm_gate(
    const float* __restrict__ o, const float* __restrict__ g, const float* __restrict__ w,
    __half* __restrict__ oh, __half* __restrict__ ol)
{
    int row = blockIdx.x;
    size_t base = (size_t)row * DV_;
    int tid = threadIdx.x;
    float x[4];
    *(float4*)x = *(const float4*)(o + base + tid*4);
    float ss = x[0]*x[0] + x[1]*x[1] + x[2]*x[2] + x[3]*x[3];
#pragma unroll
    for (int off = 16; off; off >>= 1) ss += __shfl_xor_sync(0xffffffffu, ss, off);
    __shared__ float ws[4];
    if ((tid & 31) == 0) ws[tid >> 5] = ss;
    __syncthreads();
    float tot = ws[0] + ws[1] + ws[2] + ws[3];
    float scale = rsqrtf(tot * (1.f/512.f) + 1e-5f);
    float gv[4], wv[4];
    *(float4*)gv = *(const float4*)(g + base + tid*4);
    *(float4*)wv = *(const float4*)(w + tid*4);
#pragma unroll
    for (int u = 0; u < 4; u++) {
        float sg = gv[u] / (1.f + expf(-gv[u]));
        float r = x[u] * scale * wv[u] * sg;
        __half hi = __float2half(r);
        oh[base + tid*4 + u] = hi;
        ol[base + tid*4 + u] = __float2half(r - __half2float(hi));
    }
}

// ---------------- launch ----------------
extern "C" void kernel_launch(void* const* d_in, const int* in_sizes, int n_in,
                              void* d_out, int out_size)
{
    const float* hs = (const float*)d_in[0];
    const float* Wq = (const float*)d_in[1];
    const float* Wk = (const float*)d_in[2];
    const float* Wv = (const float*)d_in[3];
    const float* Wg = (const float*)d_in[4];
    const float* Wo = (const float*)d_in[5];
    const float* gw = (const float*)d_in[6];
    float* out = (float*)d_out;

    float *q, *k, *v, *g, *o, *rc, *rs;
    cudaGetSymbolAddress((void**)&q,  g_q);
    cudaGetSymbolAddress((void**)&k,  g_k);
    cudaGetSymbolAddress((void**)&v,  g_v);
    cudaGetSymbolAddress((void**)&g,  g_g);
    cudaGetSymbolAddress((void**)&o,  g_o);
    cudaGetSymbolAddress((void**)&rc, g_rc);
    cudaGetSymbolAddress((void**)&rs, g_rs);

    __half *hsh, *wq, *wk, *wv, *wg, *wo, *oh, *ol;
    cudaGetSymbolAddress((void**)&hsh, g_hsh);
    cudaGetSymbolAddress((void**)&wq, g_wq);
    cudaGetSymbolAddress((void**)&wk, g_wk);
    cudaGetSymbolAddress((void**)&wv, g_wv);
    cudaGetSymbolAddress((void**)&wg, g_wg);
    cudaGetSymbolAddress((void**)&wo, g_wo);
    cudaGetSymbolAddress((void**)&oh, g_oh);  cudaGetSymbolAddress((void**)&ol, g_ol);

    cudaFuncSetAttribute(ret_intra, cudaFuncAttributeMaxDynamicSharedMemorySize, 147456);
    cudaFuncSetAttribute(ret_inter, cudaFuncAttributeMaxDynamicSharedMemorySize, 212992);
    cudaFuncSetAttribute(gemm_mma<true>,  cudaFuncAttributeMaxDynamicSharedMemorySize, GEMM_SMEM);
    cudaFuncSetAttribute(gemm_mma<false>, cudaFuncAttributeMaxDynamicSharedMemorySize, GEMM_SMEM);

    dim3 tb(32, 8);
    conv_f16<<<(MR*2048/4 + 255)/256, 256>>>(hs, hsh, MR*2048/4);
    tconv<<<dim3(64, 64),  tb>>>(Wq, wq, 2048, 2048);
    tconv<<<dim3(64, 64),  tb>>>(Wk, wk, 2048, 2048);
    tconv<<<dim3(128, 64), tb>>>(Wv, wv, 2048, 4096);

    // all input projections 1-term fp16
    gemm_mma<false><<<dim3(16, 32), 256, GEMM_SMEM>>>(hsh, hsh, wq, q, MR, 2048, 2048);
    gemm_mma<false><<<dim3(16, 32), 256, GEMM_SMEM>>>(hsh, hsh, wk, k, MR, 2048, 2048);
    gemm_mma<false><<<dim3(32, 32), 256, GEMM_SMEM>>>(hsh, hsh, wv, v, MR, 4096, 2048);

    tconv<<<dim3(128, 64), tb>>>(Wg, wg, 2048, 4096);
    gemm_mma<false><<<dim3(32, 32), 256, GEMM_SMEM>>>(hsh, hsh, wg, g, MR, 4096, 2048);
    tconv<<<dim3(64, 128), tb>>>(Wo, wo, 4096, 2048);

    rope_table<<<1024, 256>>>(rc, rs);
    rope_apply<<<(B_*T_*H_*128)/256, 256>>>(q, k, rc, rs);

    ret_intra<<<B_*H_*NCH, 256, 147456>>>(q, k, v, o);
    ret_inter<<<B_*H_*8,   256, 212992>>>(q, k, v, o);

    norm_gate<<<MR*H_, 128>>>(o, g, gw, oh, ol);

    // output projection stays 2-term (error passes straight to output)
    gemm_mma<true><<<dim3(16, 32), 256, GEMM_SMEM>>>(oh, ol, wo, out, MR, 2048, 4096);
}

// round 13
// speedup vs baseline: 1.6906x; 1.0772x over previous
#include <cuda_runtime.h>
#include <cuda_fp16.h>
#include <math.h>
#include <stdint.h>

#define B_   2
#define T_   2048
#define H_   8
#define DK_  256
#define DV_  512
#define C_   64
#define NCH  32            // T_/C_
#define MR   (B_*T_)       // 4096 rows

typedef unsigned long long u64;

// ---------------- scratch (no allocations allowed) ----------------
__device__ float g_q[(size_t)MR*H_*DK_];   // [b,t,h,dk]
__device__ float g_k[(size_t)MR*H_*DK_];
__device__ float g_v[(size_t)MR*H_*DV_];   // [b,t,h,dv]
__device__ float g_g[(size_t)MR*H_*DV_];
__device__ float g_o[(size_t)MR*H_*DV_];
__device__ float g_rc[T_*128];
__device__ float g_rs[T_*128];

// fp16 operand buffers
__device__ __half g_hsh[(size_t)MR*2048];
__device__ __half g_wq[(size_t)2048*2048];
__device__ __half g_wk[(size_t)2048*2048];
__device__ __half g_wv[(size_t)4096*2048];
__device__ __half g_wg[(size_t)4096*2048];
__device__ __half g_wo[(size_t)2048*4096];
__device__ __half g_oh[(size_t)MR*4096];

// ================= PTX helpers =================
__device__ __forceinline__ uint32_t smem_u32(const void* p) {
    uint32_t a;
    asm("{ .reg .u64 t; cvta.to.shared.u64 t, %1; cvt.u32.u64 %0, t; }" : "=r"(a) : "l"(p));
    return a;
}
__device__ __forceinline__ void cpa16(uint32_t s, const void* g) {
    asm volatile("cp.async.cg.shared.global [%0], [%1], 16;" :: "r"(s), "l"(g));
}
__device__ __forceinline__ void cp_commit() {
    asm volatile("cp.async.commit_group;" ::: "memory");
}
__device__ __forceinline__ void cp_wait2() {
    asm volatile("cp.async.wait_group 2;" ::: "memory");
}
__device__ __forceinline__ void ldm4(uint32_t* r, uint32_t a) {
    asm volatile("ldmatrix.sync.aligned.m8n8.x4.shared.b16 {%0,%1,%2,%3}, [%4];"
        : "=r"(r[0]), "=r"(r[1]), "=r"(r[2]), "=r"(r[3]) : "r"(a));
}
__device__ __forceinline__ void mma16816(float* c, const uint32_t* a, const uint32_t* b) {
    asm volatile(
        "mma.sync.aligned.m16n8k16.row.col.f32.f16.f16.f32 "
        "{%0,%1,%2,%3}, {%4,%5,%6,%7}, {%8,%9}, {%0,%1,%2,%3};"
        : "+f"(c[0]), "+f"(c[1]), "+f"(c[2]), "+f"(c[3])
        : "r"(a[0]), "r"(a[1]), "r"(a[2]), "r"(a[3]), "r"(b[0]), "r"(b[1]));
}
// packed f32x2
__device__ __forceinline__ u64 pack2(float x, float y) {
    u64 r; asm("mov.b64 %0, {%1, %2};" : "=l"(r) : "f"(x), "f"(y)); return r;
}
__device__ __forceinline__ u64 bcast2(float x) { return pack2(x, x); }
#define FMA2(d, a, b) asm("fma.rn.f32x2 %0, %1, %2, %0;" : "+l"(d) : "l"(a), "l"(b))
__device__ __forceinline__ void unpack2(u64 v, float& lo, float& hi) {
    asm("mov.b64 {%0, %1}, %2;" : "=f"(lo), "=f"(hi) : "l"(v));
}
__device__ __forceinline__ float gpow(float lg2, float e) {
    return exp2f(e * lg2);
}

// ================= conversion kernels =================
__global__ void conv_f16(const float* __restrict__ x, __half* __restrict__ h, int n4)
{
    int i = blockIdx.x * 256 + threadIdx.x;
    if (i >= n4) return;
    float4 v = *(const float4*)(x + (size_t)i * 4);
    __half2 a = __floats2half2_rn(v.x, v.y);
    __half2 b = __floats2half2_rn(v.z, v.w);
    *(uint2*)(h + (size_t)i*4) = make_uint2(
        *(uint32_t*)&a, *(uint32_t*)&b);
}

// W[K,N] -> Wt fp16 [N,K]
__global__ void tconv(const float* __restrict__ W, __half* __restrict__ h, int K, int N)
{
    __shared__ float tile[32][33];
    int k0 = blockIdx.y * 32, n0 = blockIdx.x * 32;
    int tx = threadIdx.x, ty = threadIdx.y;
#pragma unroll
    for (int i = 0; i < 4; i++)
        tile[ty + 8*i][tx] = W[(size_t)(k0 + ty + 8*i) * N + n0 + tx];
    __syncthreads();
#pragma unroll
    for (int i = 0; i < 4; i++)
        h[(size_t)(n0 + ty + 8*i) * K + k0 + tx] = __float2half(tile[tx][ty + 8*i]);
}

// ================= HMMA GEMM: C[M,N] = (Ah[+Al])[M,K] @ Bt[N,K]^T =================
// fp16 operands, fp32 accum. CTA tile 128x128, BK=32, 4-stage cp.async.
#define OAH 0u
#define OAL 10240u
#define OBH 20480u
#define SSTG 30720u
#define GEMM_SMEM (4*30720)

template<bool TWO>
__global__ __launch_bounds__(256, 1) void gemm_mma(
    const __half* __restrict__ Ah, const __half* __restrict__ Al,
    const __half* __restrict__ Bh,
    float* __restrict__ Cc, int M, int N, int K)
{
    extern __shared__ __align__(128) char smc[];
    const uint32_t sb = smem_u32(smc);
    const int tid = threadIdx.x;
    const int lane = tid & 31, w = tid >> 5;
    const int wm = w & 3, wn = w >> 2;
    const int m0 = blockIdx.y * 128, n0 = blockIdx.x * 128;
    const int NC = K >> 5;

    float c[2][8][4] = {};

    auto load_stage = [&](int s, int k0) {
        uint32_t base = sb + (uint32_t)s * SSTG;
#pragma unroll
        for (int i = 0; i < 2; i++) {
            int idx = tid + (i << 8);
            int r = idx >> 2, kc = idx & 3;
            uint32_t da = base + r * 80 + kc * 16;
            size_t ga = (size_t)(m0 + r) * K + k0 + kc * 8;
            cpa16(da + OAH, Ah + ga);
            if (TWO) cpa16(da + OAL, Al + ga);
            size_t gb = (size_t)(n0 + r) * K + k0 + kc * 8;
            cpa16(da + OBH, Bh + gb);
        }
    };

    load_stage(0, 0);  cp_commit();
    load_stage(1, 32); cp_commit();
    load_stage(2, 64); cp_commit();

    for (int i = 0; i < NC; i++) {
        cp_wait2();
        __syncthreads();
        if (i + 3 < NC) load_stage((i + 3) & 3, (i + 3) << 5);
        cp_commit();

        uint32_t base = sb + (uint32_t)(i & 3) * SSTG;
#pragma unroll
        for (int ks = 0; ks < 2; ks++) {
            uint32_t ah[2][4], al[2][4];
#pragma unroll
            for (int mt = 0; mt < 2; mt++) {
                int row = wm * 32 + mt * 16 + (lane & 15);
                int kc = ks * 2 + (lane >> 4);
                uint32_t ad = base + row * 80 + kc * 16;
                ldm4(ah[mt], ad + OAH);
                if (TWO) ldm4(al[mt], ad + OAL);
            }
            uint32_t bh[4][4];
#pragma unroll
            for (int np = 0; np < 4; np++) {
                int row = wn * 64 + np * 16 + (lane & 7) + ((lane & 16) >> 1);
                int kc = ks * 2 + ((lane >> 3) & 1);
                uint32_t bd = base + row * 80 + kc * 16;
                ldm4(bh[np], bd + OBH);
            }
#pragma unroll
            for (int mt = 0; mt < 2; mt++)
#pragma unroll
                for (int np = 0; np < 4; np++)
#pragma unroll
                    for (int hf = 0; hf < 2; hf++) {
                        float* cc = c[mt][np * 2 + hf];
                        mma16816(cc, ah[mt], &bh[np][hf * 2]);
                        if (TWO) mma16816(cc, al[mt], &bh[np][hf * 2]);
                    }
        }
        __syncthreads();
    }

    const int rbase = m0 + wm * 32 + (lane >> 2);
    const int cbase = n0 + wn * 64 + (lane & 3) * 2;
#pragma unroll
    for (int mt = 0; mt < 2; mt++)
#pragma unroll
        for (int nt = 0; nt < 8; nt++) {
            *(float2*)&Cc[(size_t)(rbase + mt * 16) * N + cbase + nt * 8] =
                make_float2(c[mt][nt][0], c[mt][nt][1]);
            *(float2*)&Cc[(size_t)(rbase + mt * 16 + 8) * N + cbase + nt * 8] =
                make_float2(c[mt][nt][2], c[mt][nt][3]);
        }
}

// ---------------- rotary (fp32, mirrors the reference's own f32 math) --------
__global__ void rope_table(float* __restrict__ rc, float* __restrict__ rs)
{
    int idx = blockIdx.x * blockDim.x + threadIdx.x;   // t*128 + j
    if (idx >= T_*128) return;
    int t = idx >> 7, j = idx & 127;
    float inv = 1.0f / powf(10000.0f, (float)j * (1.0f/128.0f));
    float a = (float)t * inv;
    float s, c;
    sincosf(a, &s, &c);
    rc[idx] = c;
    rs[idx] = s;
}

__global__ void rope_apply(float* __restrict__ q, float* __restrict__ k,
                           const float* __restrict__ rc, const float* __restrict__ rs)
{
    int idx = blockIdx.x * blockDim.x + threadIdx.x;
    if (idx >= B_*T_*H_*128) return;
    int j = idx & 127;
    int h = (idx >> 7) & (H_-1);
    int t = (idx >> 10) & (T_-1);
    int b = idx >> 21;
    float c = rc[t*128 + j], s = rs[t*128 + j];
    size_t base = ((size_t)(b*T_ + t)*H_ + h)*DK_;
    float x1 = q[base + j], x2 = q[base + 128 + j];
    q[base + j]       = x1*c - x2*s;
    q[base + 128 + j] = x2*c + x1*s;
    x1 = k[base + j]; x2 = k[base + 128 + j];
    k[base + j]       = x1*c - x2*s;
    k[base + 128 + j] = x2*c + x1*s;
}

// ---------------- retention: intra-chunk (fully parallel) ----------------
__global__ __launch_bounds__(256) void ret_intra(
    const float* __restrict__ q, const float* __restrict__ k,
    const float* __restrict__ v, float* __restrict__ o)
{
    extern __shared__ float sm[];
    float* sQt = sm;              // [256][64]
    float* sKt = sm + 16384;      // [256][64]
    float* sA  = sm + 32768;      // [64][64]
    float* sV  = sm;              // reuse [64][512]
    __shared__ float gp[64];

    int bx = blockIdx.x;
    int n = bx % NCH; int h = (bx / NCH) % H_; int b = bx / (NCH*H_);
    int tid = threadIdx.x;
    float gamma = 1.f - exp2f(-5.f - (float)h);
    float lg2 = log2f(gamma);
    if (tid < 64) gp[tid] = gpow(lg2, (float)tid);

    const size_t qbase = ((size_t)(b*T_ + n*C_)*H_ + h)*DK_;
#pragma unroll
    for (int r = 0; r < 16; r++) {
        int idx = tid + 256*r;
        int row = idx >> 6;
        int d4  = (idx & 63) << 2;
        float4 qv = *(const float4*)(q + qbase + (size_t)row*H_*DK_ + d4);
        sQt[(d4+0)*64 + row] = qv.x * 0.0625f;
        sQt[(d4+1)*64 + row] = qv.y * 0.0625f;
        sQt[(d4+2)*64 + row] = qv.z * 0.0625f;
        sQt[(d4+3)*64 + row] = qv.w * 0.0625f;
        float4 kv = *(const float4*)(k + qbase + (size_t)row*H_*DK_ + d4);
        sKt[(d4+0)*64 + row] = kv.x;
        sKt[(d4+1)*64 + row] = kv.y;
        sKt[(d4+2)*64 + row] = kv.z;
        sKt[(d4+3)*64 + row] = kv.w;
    }
    __syncthreads();
    {
        int ti = tid >> 4, tj = tid & 15;
        u64 acc2[4][2] = {};
        for (int d = 0; d < 256; d++) {
            float4 qa = *(float4*)(sQt + d*64 + ti*4);
            ulonglong2 ka = *(ulonglong2*)(sKt + d*64 + tj*4);
            u64 q0 = bcast2(qa.x), q1 = bcast2(qa.y), q2 = bcast2(qa.z), q3 = bcast2(qa.w);
            FMA2(acc2[0][0], q0, ka.x); FMA2(acc2[0][1], q0, ka.y);
            FMA2(acc2[1][0], q1, ka.x); FMA2(acc2[1][1], q1, ka.y);
            FMA2(acc2[2][0], q2, ka.x); FMA2(acc2[2][1], q2, ka.y);
            FMA2(acc2[3][0], q3, ka.x); FMA2(acc2[3][1], q3, ka.y);
        }
#pragma unroll
        for (int a = 0; a < 4; a++) {
            float f[4];
            unpack2(acc2[a][0], f[0], f[1]);
            unpack2(acc2[a][1], f[2], f[3]);
#pragma unroll
            for (int c = 0; c < 4; c++) {
                int i = ti*4 + a, j = tj*4 + c;
                sA[i*64 + j] = (i >= j) ? f[c] * gp[i-j] : 0.f;
            }
        }
    }
    __syncthreads();
    const size_t vbase = ((size_t)(b*T_ + n*C_)*H_ + h)*DV_;
#pragma unroll
    for (int r = 0; r < 32; r++) {
        int idx = tid + 256*r;
        int row = idx >> 7;
        int v4  = (idx & 127) << 2;
        *(float4*)(sV + row*512 + v4) =
            *(const float4*)(v + vbase + (size_t)row*H_*DV_ + v4);
    }
    __syncthreads();
    int ty = tid >> 6;
    int tx = tid & 63;
    for (int ii = 0; ii < 16; ii++) {
        int i = ty*16 + ii;
        u64 acc2[4] = {};
        for (int j = 0; j < 64; j++) {
            u64 ab = bcast2(sA[i*64 + j]);
            ulonglong2 v0 = *(ulonglong2*)(sV + j*512 + tx*8);
            ulonglong2 v1 = *(ulonglong2*)(sV + j*512 + tx*8 + 4);
            FMA2(acc2[0], ab, v0.x); FMA2(acc2[1], ab, v0.y);
            FMA2(acc2[2], ab, v1.x); FMA2(acc2[3], ab, v1.y);
        }
        float* op = o + vbase + (size_t)i*H_*DV_ + tx*8;
        *(ulonglong2*)op       = make_ulonglong2(acc2[0], acc2[1]);
        *(ulonglong2*)(op + 4) = make_ulonglong2(acc2[2], acc2[3]);
    }
}

// ---------------- retention: inter-chunk scan ----------------
__global__ __launch_bounds__(256) void ret_inter(
    const float* __restrict__ q, const float* __restrict__ k,
    const float* __restrict__ v, float* __restrict__ o)
{
    extern __shared__ float sm[];
    float* S   = sm;
    float* sQt = sm + 16384;
    float* sK  = sm + 32768;
    float* sV  = sm + 49152;
    __shared__ float qdv[64], kdv[64];

    int bx = blockIdx.x;
    int vs = bx & 7; int h = (bx >> 3) & 7; int b = bx >> 6;
    int v0 = vs * 64;
    int tid = threadIdx.x;
    float gamma = 1.f - exp2f(-5.f - (float)h);
    float lg2 = log2f(gamma);
    if (tid < 64) {
        qdv[tid] = 0.0625f * gpow(lg2, (float)(tid + 1));
        kdv[tid] = gpow(lg2, (float)(63 - tid));
    }
    float gC = gpow(lg2, 64.f);
    u64 gC2 = bcast2(gC);
#pragma unroll
    for (int r = 0; r < 64; r++) S[tid + 256*r] = 0.f;
    __syncthreads();

    for (int n = 0; n < NCH; n++) {
        const size_t qbase = ((size_t)(b*T_ + n*C_)*H_ + h)*DK_;
        const size_t vbase = ((size_t)(b*T_ + n*C_)*H_ + h)*DV_ + v0;
#pragma unroll
        for (int r = 0; r < 16; r++) {
            int idx = tid + 256*r;
            int row = idx >> 6;
            int d4  = (idx & 63) << 2;
            float4 qv = *(const float4*)(q + qbase + (size_t)row*H_*DK_ + d4);
            float qs = qdv[row];
            sQt[(d4+0)*64 + row] = qv.x*qs;
            sQt[(d4+1)*64 + row] = qv.y*qs;
            sQt[(d4+2)*64 + row] = qv.z*qs;
            sQt[(d4+3)*64 + row] = qv.w*qs;
            float4 kv = *(const float4*)(k + qbase + (size_t)row*H_*DK_ + d4);
            float ks = kdv[row];
            *(float4*)(sK + row*256 + d4) =
                make_float4(kv.x*ks, kv.y*ks, kv.z*ks, kv.w*ks);
        }
#pragma unroll
        for (int r = 0; r < 4; r++) {
            int idx = tid + 256*r;
            int row = idx >> 4;
            int v4  = (idx & 15) << 2;
            *(float4*)(sV + row*64 + v4) =
                *(const float4*)(v + vbase + (size_t)row*H_*DV_ + v4);
        }
        __syncthreads();

        if (n > 0) {    // o_inter = (Q*qd) @ S
            int ti = tid >> 4, tv = tid & 15;
            int i0 = ti*4, w0 = tv*4;
            u64 acc2[4][2] = {};
            for (int d = 0; d < 256; d++) {
                float4 qa = *(float4*)(sQt + d*64 + i0);
                ulonglong2 sa = *(ulonglong2*)(S + d*64 + w0);
                u64 q0 = bcast2(qa.x), q1 = bcast2(qa.y), q2 = bcast2(qa.z), q3 = bcast2(qa.w);
                FMA2(acc2[0][0], q0, sa.x); FMA2(acc2[0][1], q0, sa.y);
                FMA2(acc2[1][0], q1, sa.x); FMA2(acc2[1][1], q1, sa.y);
                FMA2(acc2[2][0], q2, sa.x); FMA2(acc2[2][1], q2, sa.y);
                FMA2(acc2[3][0], q3, sa.x); FMA2(acc2[3][1], q3, sa.y);
            }
#pragma unroll
            for (int a = 0; a < 4; a++) {
                float f[4];
                unpack2(acc2[a][0], f[0], f[1]);
                unpack2(acc2[a][1], f[2], f[3]);
                float* op = o + ((size_t)(b*T_ + n*C_ + i0 + a)*H_ + h)*DV_ + v0 + w0;
                float4 cur = *(float4*)op;
                cur.x += f[0]; cur.y += f[1]; cur.z += f[2]; cur.w += f[3];
                *(float4*)op = cur;
            }
        }
        __syncthreads();   // all S reads done before update

        {   // S = gC*S + (K*kd)^T @ V
            int td = tid >> 3, tw = tid & 7;
            int d0 = td*8, w0 = tw*8;
            u64 acc2[8][4] = {};
            for (int j = 0; j < 64; j++) {
                float ka[8];
                *(float4*)&ka[0] = *(float4*)(sK + j*256 + d0);
                *(float4*)&ka[4] = *(float4*)(sK + j*256 + d0 + 4);
                ulonglong2 va0 = *(ulonglong2*)(sV + j*64 + w0);
                ulonglong2 va1 = *(ulonglong2*)(sV + j*64 + w0 + 4);
#pragma unroll
                for (int a = 0; a < 8; a++) {
                    u64 kb = bcast2(ka[a]);
                    FMA2(acc2[a][0], kb, va0.x);
                    FMA2(acc2[a][1], kb, va0.y);
                    FMA2(acc2[a][2], kb, va1.x);
                    FMA2(acc2[a][3], kb, va1.y);
                }
            }
#pragma unroll
            for (int a = 0; a < 8; a++)
#pragma unroll
                for (int c2 = 0; c2 < 4; c2++) {
                    u64* sp = (u64*)(S + (d0+a)*64 + w0 + c2*2);
                    u64 sv = *sp;
                    FMA2(acc2[a][c2], gC2, sv);   // acc = gC*S + acc
                    *sp = acc2[a][c2];
                }
        }
        __syncthreads();
    }
}

// ---------------- RMSNorm + swish gate -> fp16 ----------------
__global__ __launch_bounds__(128) void norm_gate(
    const float* __restrict__ o, const float* __restrict__ g, const float* __restrict__ w,
    __half* __restrict__ oh)
{
    int row = blockIdx.x;
    size_t base = (size_t)row * DV_;
    int tid = threadIdx.x;
    float x[4];
    *(float4*)x = *(const float4*)(o + base + tid*4);
    float ss = x[0]*x[0] + x[1]*x[1] + x[2]*x[2] + x[3]*x[3];
#pragma unroll
    for (int off = 16; off; off >>= 1) ss += __shfl_xor_sync(0xffffffffu, ss, off);
    __shared__ float ws[4];
    if ((tid & 31) == 0) ws[tid >> 5] = ss;
    __syncthreads();
    float tot = ws[0] + ws[1] + ws[2] + ws[3];
    float scale = rsqrtf(tot * (1.f/512.f) + 1e-5f);
    float gv[4], wv[4];
    *(float4*)gv = *(const float4*)(g + base + tid*4);
    *(float4*)wv = *(const float4*)(w + tid*4);
    __half2 r01, r23;
    {
        float r0 = x[0]*scale*wv[0]*(gv[0]/(1.f+expf(-gv[0])));
        float r1 = x[1]*scale*wv[1]*(gv[1]/(1.f+expf(-gv[1])));
        float r2 = x[2]*scale*wv[2]*(gv[2]/(1.f+expf(-gv[2])));
        float r3 = x[3]*scale*wv[3]*(gv[3]/(1.f+expf(-gv[3])));
        r01 = __floats2half2_rn(r0, r1);
        r23 = __floats2half2_rn(r2, r3);
    }
    *(uint2*)(oh + base + tid*4) = make_uint2(*(uint32_t*)&r01, *(uint32_t*)&r23);
}

// ---------------- launch ----------------
extern "C" void kernel_launch(void* const* d_in, const int* in_sizes, int n_in,
                              void* d_out, int out_size)
{
    const float* hs = (const float*)d_in[0];
    const float* Wq = (const float*)d_in[1];
    const float* Wk = (const float*)d_in[2];
    const float* Wv = (const float*)d_in[3];
    const float* Wg = (const float*)d_in[4];
    const float* Wo = (const float*)d_in[5];
    const float* gw = (const float*)d_in[6];
    float* out = (float*)d_out;

    float *q, *k, *v, *g, *o, *rc, *rs;
    cudaGetSymbolAddress((void**)&q,  g_q);
    cudaGetSymbolAddress((void**)&k,  g_k);
    cudaGetSymbolAddress((void**)&v,  g_v);
    cudaGetSymbolAddress((void**)&g,  g_g);
    cudaGetSymbolAddress((void**)&o,  g_o);
    cudaGetSymbolAddress((void**)&rc, g_rc);
    cudaGetSymbolAddress((void**)&rs, g_rs);

    __half *hsh, *wq, *wk, *wv, *wg, *wo, *oh;
    cudaGetSymbolAddress((void**)&hsh, g_hsh);
    cudaGetSymbolAddress((void**)&wq, g_wq);
    cudaGetSymbolAddress((void**)&wk, g_wk);
    cudaGetSymbolAddress((void**)&wv, g_wv);
    cudaGetSymbolAddress((void**)&wg, g_wg);
    cudaGetSymbolAddress((void**)&wo, g_wo);
    cudaGetSymbolAddress((void**)&oh, g_oh);

    cudaFuncSetAttribute(ret_intra, cudaFuncAttributeMaxDynamicSharedMemorySize, 147456);
    cudaFuncSetAttribute(ret_inter, cudaFuncAttributeMaxDynamicSharedMemorySize, 212992);
    cudaFuncSetAttribute(gemm_mma<false>, cudaFuncAttributeMaxDynamicSharedMemorySize, GEMM_SMEM);

    dim3 tb(32, 8);
    // positions 1-3: conversions; positions 4-7: GEMMs (for ncu capture window)
    conv_f16<<<(MR*2048/4 + 255)/256, 256>>>(hs, hsh, MR*2048/4);
    tconv<<<dim3(64, 64),  tb>>>(Wq, wq, 2048, 2048);
    tconv<<<dim3(64, 64),  tb>>>(Wk, wk, 2048, 2048);

    gemm_mma<false><<<dim3(16, 32), 256, GEMM_SMEM>>>(hsh, hsh, wq, q, MR, 2048, 2048);
    gemm_mma<false><<<dim3(16, 32), 256, GEMM_SMEM>>>(hsh, hsh, wk, k, MR, 2048, 2048);

    tconv<<<dim3(128, 64), tb>>>(Wv, wv, 2048, 4096);
    gemm_mma<false><<<dim3(32, 32), 256, GEMM_SMEM>>>(hsh, hsh, wv, v, MR, 4096, 2048);
    tconv<<<dim3(128, 64), tb>>>(Wg, wg, 2048, 4096);
    gemm_mma<false><<<dim3(32, 32), 256, GEMM_SMEM>>>(hsh, hsh, wg, g, MR, 4096, 2048);
    tconv<<<dim3(64, 128), tb>>>(Wo, wo, 4096, 2048);

    rope_table<<<1024, 256>>>(rc, rs);
    rope_apply<<<(B_*T_*H_*128)/256, 256>>>(q, k, rc, rs);

    ret_intra<<<B_*H_*NCH, 256, 147456>>>(q, k, v, o);
    ret_inter<<<B_*H_*8,   256, 212992>>>(q, k, v, o);

    norm_gate<<<MR*H_, 128>>>(o, g, gw, oh);

    // output projection now also 1-term fp16
    gemm_mma<false><<<dim3(16, 32), 256, GEMM_SMEM>>>(oh, oh, wo, out, MR, 2048, 4096);
}

// round 14
// speedup vs baseline: 1.9406x; 1.1479x over previous
#include <cuda_runtime.h>
#include <cuda_fp16.h>
#include <math.h>
#include <stdint.h>

#define B_   2
#define T_   2048
#define H_   8
#define DK_  256
#define DV_  512
#define C_   64
#define NCH  32            // T_/C_
#define MR   (B_*T_)       // 4096 rows

typedef unsigned long long u64;

// ---------------- scratch (no allocations allowed) ----------------
__device__ float g_q[(size_t)MR*H_*DK_];   // [b,t,h,dk]
__device__ float g_k[(size_t)MR*H_*DK_];
__device__ float g_v[(size_t)MR*H_*DV_];   // [b,t,h,dv]
__device__ float g_g[(size_t)MR*H_*DV_];
__device__ float g_o[(size_t)MR*H_*DV_];
__device__ float g_rc[T_*128];
__device__ float g_rs[T_*128];

// fp16 operand buffers
__device__ __half g_hsh[(size_t)MR*2048];
__device__ __half g_wq[(size_t)2048*2048];
__device__ __half g_wk[(size_t)2048*2048];
__device__ __half g_wv[(size_t)4096*2048];
__device__ __half g_wg[(size_t)4096*2048];
__device__ __half g_wo[(size_t)2048*4096];
__device__ __half g_oh[(size_t)MR*4096];

// ================= PTX helpers =================
__device__ __forceinline__ uint32_t smem_u32(const void* p) {
    uint32_t a;
    asm("{ .reg .u64 t; cvta.to.shared.u64 t, %1; cvt.u32.u64 %0, t; }" : "=r"(a) : "l"(p));
    return a;
}
__device__ __forceinline__ void cpa16(uint32_t s, const void* g) {
    asm volatile("cp.async.cg.shared.global [%0], [%1], 16;" :: "r"(s), "l"(g));
}
__device__ __forceinline__ void cp_commit() {
    asm volatile("cp.async.commit_group;" ::: "memory");
}
__device__ __forceinline__ void cp_wait2() {
    asm volatile("cp.async.wait_group 2;" ::: "memory");
}
__device__ __forceinline__ void ldm4(uint32_t* r, uint32_t a) {
    asm volatile("ldmatrix.sync.aligned.m8n8.x4.shared.b16 {%0,%1,%2,%3}, [%4];"
        : "=r"(r[0]), "=r"(r[1]), "=r"(r[2]), "=r"(r[3]) : "r"(a));
}
__device__ __forceinline__ void mma16816(float* c, const uint32_t* a, const uint32_t* b) {
    asm volatile(
        "mma.sync.aligned.m16n8k16.row.col.f32.f16.f16.f32 "
        "{%0,%1,%2,%3}, {%4,%5,%6,%7}, {%8,%9}, {%0,%1,%2,%3};"
        : "+f"(c[0]), "+f"(c[1]), "+f"(c[2]), "+f"(c[3])
        : "r"(a[0]), "r"(a[1]), "r"(a[2]), "r"(a[3]), "r"(b[0]), "r"(b[1]));
}
// packed f32x2
__device__ __forceinline__ u64 pack2(float x, float y) {
    u64 r; asm("mov.b64 %0, {%1, %2};" : "=l"(r) : "f"(x), "f"(y)); return r;
}
__device__ __forceinline__ u64 bcast2(float x) { return pack2(x, x); }
#define FMA2(d, a, b) asm("fma.rn.f32x2 %0, %1, %2, %0;" : "+l"(d) : "l"(a), "l"(b))
__device__ __forceinline__ void unpack2(u64 v, float& lo, float& hi) {
    asm("mov.b64 {%0, %1}, %2;" : "=f"(lo), "=f"(hi) : "l"(v));
}
__device__ __forceinline__ float gpow(float lg2, float e) {
    return exp2f(e * lg2);
}

// ================= conversion kernels =================
__global__ void conv_f16(const float* __restrict__ x, __half* __restrict__ h, int n4)
{
    int i = blockIdx.x * 256 + threadIdx.x;
    if (i >= n4) return;
    float4 v = *(const float4*)(x + (size_t)i * 4);
    __half2 a = __floats2half2_rn(v.x, v.y);
    __half2 b = __floats2half2_rn(v.z, v.w);
    *(uint2*)(h + (size_t)i*4) = make_uint2(
        *(uint32_t*)&a, *(uint32_t*)&b);
}

// W[K,N] -> Wt fp16 [N,K]
__global__ void tconv(const float* __restrict__ W, __half* __restrict__ h, int K, int N)
{
    __shared__ float tile[32][33];
    int k0 = blockIdx.y * 32, n0 = blockIdx.x * 32;
    int tx = threadIdx.x, ty = threadIdx.y;
#pragma unroll
    for (int i = 0; i < 4; i++)
        tile[ty + 8*i][tx] = W[(size_t)(k0 + ty + 8*i) * N + n0 + tx];
    __syncthreads();
#pragma unroll
    for (int i = 0; i < 4; i++)
        h[(size_t)(n0 + ty + 8*i) * K + k0 + tx] = __float2half(tile[tx][ty + 8*i]);
}

// ================= HMMA GEMM: C[M,N] = A[M,K] @ Bt[N,K]^T =================
// fp16 operands, fp32 accum. CTA tile 128x128, BK=32, 4-stage cp.async.
// 20KB/stage, 80KB total -> 2 CTAs per SM.
#define OAH 0u
#define OBH 10240u
#define SSTG 20480u
#define GEMM_SMEM (4*20480)

__global__ __launch_bounds__(256, 2) void gemm_mma(
    const __half* __restrict__ Ah, const __half* __restrict__ Bh,
    float* __restrict__ Cc, int M, int N, int K)
{
    extern __shared__ __align__(128) char smc[];
    const uint32_t sb = smem_u32(smc);
    const int tid = threadIdx.x;
    const int lane = tid & 31, w = tid >> 5;
    const int wm = w & 3, wn = w >> 2;
    const int m0 = blockIdx.y * 128, n0 = blockIdx.x * 128;
    const int NC = K >> 5;

    float c[2][8][4] = {};

    auto load_stage = [&](int s, int k0) {
        uint32_t base = sb + (uint32_t)s * SSTG;
#pragma unroll
        for (int i = 0; i < 2; i++) {
            int idx = tid + (i << 8);
            int r = idx >> 2, kc = idx & 3;
            uint32_t da = base + r * 80 + kc * 16;
            size_t ga = (size_t)(m0 + r) * K + k0 + kc * 8;
            cpa16(da + OAH, Ah + ga);
            size_t gb = (size_t)(n0 + r) * K + k0 + kc * 8;
            cpa16(da + OBH, Bh + gb);
        }
    };

    load_stage(0, 0);  cp_commit();
    load_stage(1, 32); cp_commit();
    load_stage(2, 64); cp_commit();

    for (int i = 0; i < NC; i++) {
        cp_wait2();
        __syncthreads();
        if (i + 3 < NC) load_stage((i + 3) & 3, (i + 3) << 5);
        cp_commit();

        uint32_t base = sb + (uint32_t)(i & 3) * SSTG;
#pragma unroll
        for (int ks = 0; ks < 2; ks++) {
            uint32_t ah[2][4];
#pragma unroll
            for (int mt = 0; mt < 2; mt++) {
                int row = wm * 32 + mt * 16 + (lane & 15);
                int kc = ks * 2 + (lane >> 4);
                ldm4(ah[mt], base + OAH + row * 80 + kc * 16);
            }
            uint32_t bh[4][4];
#pragma unroll
            for (int np = 0; np < 4; np++) {
                int row = wn * 64 + np * 16 + (lane & 7) + ((lane & 16) >> 1);
                int kc = ks * 2 + ((lane >> 3) & 1);
                ldm4(bh[np], base + OBH + row * 80 + kc * 16);
            }
#pragma unroll
            for (int mt = 0; mt < 2; mt++)
#pragma unroll
                for (int np = 0; np < 4; np++)
#pragma unroll
                    for (int hf = 0; hf < 2; hf++)
                        mma16816(c[mt][np * 2 + hf], ah[mt], &bh[np][hf * 2]);
        }
        __syncthreads();
    }

    const int rbase = m0 + wm * 32 + (lane >> 2);
    const int cbase = n0 + wn * 64 + (lane & 3) * 2;
#pragma unroll
    for (int mt = 0; mt < 2; mt++)
#pragma unroll
        for (int nt = 0; nt < 8; nt++) {
            *(float2*)&Cc[(size_t)(rbase + mt * 16) * N + cbase + nt * 8] =
                make_float2(c[mt][nt][0], c[mt][nt][1]);
            *(float2*)&Cc[(size_t)(rbase + mt * 16 + 8) * N + cbase + nt * 8] =
                make_float2(c[mt][nt][2], c[mt][nt][3]);
        }
}

// ---------------- rotary (fp32, mirrors the reference's own f32 math) --------
__global__ void rope_table(float* __restrict__ rc, float* __restrict__ rs)
{
    int idx = blockIdx.x * blockDim.x + threadIdx.x;   // t*128 + j
    if (idx >= T_*128) return;
    int t = idx >> 7, j = idx & 127;
    float inv = 1.0f / powf(10000.0f, (float)j * (1.0f/128.0f));
    float a = (float)t * inv;
    float s, c;
    sincosf(a, &s, &c);
    rc[idx] = c;
    rs[idx] = s;
}

__global__ void rope_apply(float* __restrict__ q, float* __restrict__ k,
                           const float* __restrict__ rc, const float* __restrict__ rs)
{
    int idx = blockIdx.x * blockDim.x + threadIdx.x;
    if (idx >= B_*T_*H_*128) return;
    int j = idx & 127;
    int h = (idx >> 7) & (H_-1);
    int t = (idx >> 10) & (T_-1);
    int b = idx >> 21;
    float c = rc[t*128 + j], s = rs[t*128 + j];
    size_t base = ((size_t)(b*T_ + t)*H_ + h)*DK_;
    float x1 = q[base + j], x2 = q[base + 128 + j];
    q[base + j]       = x1*c - x2*s;
    q[base + 128 + j] = x2*c + x1*s;
    x1 = k[base + j]; x2 = k[base + 128 + j];
    k[base + j]       = x1*c - x2*s;
    k[base + 128 + j] = x2*c + x1*s;
}

// ---------------- retention: intra-chunk (fully parallel) ----------------
__global__ __launch_bounds__(256) void ret_intra(
    const float* __restrict__ q, const float* __restrict__ k,
    const float* __restrict__ v, float* __restrict__ o)
{
    extern __shared__ float sm[];
    float* sQt = sm;              // [256][64]
    float* sKt = sm + 16384;      // [256][64]
    float* sA  = sm + 32768;      // [64][64]
    float* sV  = sm;              // reuse [64][512]
    __shared__ float gp[64];

    int bx = blockIdx.x;
    int n = bx % NCH; int h = (bx / NCH) % H_; int b = bx / (NCH*H_);
    int tid = threadIdx.x;
    float gamma = 1.f - exp2f(-5.f - (float)h);
    float lg2 = log2f(gamma);
    if (tid < 64) gp[tid] = gpow(lg2, (float)tid);

    const size_t qbase = ((size_t)(b*T_ + n*C_)*H_ + h)*DK_;
#pragma unroll
    for (int r = 0; r < 16; r++) {
        int idx = tid + 256*r;
        int row = idx >> 6;
        int d4  = (idx & 63) << 2;
        float4 qv = *(const float4*)(q + qbase + (size_t)row*H_*DK_ + d4);
        sQt[(d4+0)*64 + row] = qv.x * 0.0625f;
        sQt[(d4+1)*64 + row] = qv.y * 0.0625f;
        sQt[(d4+2)*64 + row] = qv.z * 0.0625f;
        sQt[(d4+3)*64 + row] = qv.w * 0.0625f;
        float4 kv = *(const float4*)(k + qbase + (size_t)row*H_*DK_ + d4);
        sKt[(d4+0)*64 + row] = kv.x;
        sKt[(d4+1)*64 + row] = kv.y;
        sKt[(d4+2)*64 + row] = kv.z;
        sKt[(d4+3)*64 + row] = kv.w;
    }
    __syncthreads();
    {
        int ti = tid >> 4, tj = tid & 15;
        u64 acc2[4][2] = {};
        for (int d = 0; d < 256; d++) {
            float4 qa = *(float4*)(sQt + d*64 + ti*4);
            ulonglong2 ka = *(ulonglong2*)(sKt + d*64 + tj*4);
            u64 q0 = bcast2(qa.x), q1 = bcast2(qa.y), q2 = bcast2(qa.z), q3 = bcast2(qa.w);
            FMA2(acc2[0][0], q0, ka.x); FMA2(acc2[0][1], q0, ka.y);
            FMA2(acc2[1][0], q1, ka.x); FMA2(acc2[1][1], q1, ka.y);
            FMA2(acc2[2][0], q2, ka.x); FMA2(acc2[2][1], q2, ka.y);
            FMA2(acc2[3][0], q3, ka.x); FMA2(acc2[3][1], q3, ka.y);
        }
#pragma unroll
        for (int a = 0; a < 4; a++) {
            float f[4];
            unpack2(acc2[a][0], f[0], f[1]);
            unpack2(acc2[a][1], f[2], f[3]);
#pragma unroll
            for (int c = 0; c < 4; c++) {
                int i = ti*4 + a, j = tj*4 + c;
                sA[i*64 + j] = (i >= j) ? f[c] * gp[i-j] : 0.f;
            }
        }
    }
    __syncthreads();
    const size_t vbase = ((size_t)(b*T_ + n*C_)*H_ + h)*DV_;
#pragma unroll
    for (int r = 0; r < 32; r++) {
        int idx = tid + 256*r;
        int row = idx >> 7;
        int v4  = (idx & 127) << 2;
        *(float4*)(sV + row*512 + v4) =
            *(const float4*)(v + vbase + (size_t)row*H_*DV_ + v4);
    }
    __syncthreads();
    int ty = tid >> 6;
    int tx = tid & 63;
    for (int ii = 0; ii < 16; ii++) {
        int i = ty*16 + ii;
        u64 acc2[4] = {};
        for (int j = 0; j < 64; j++) {
            u64 ab = bcast2(sA[i*64 + j]);
            ulonglong2 v0 = *(ulonglong2*)(sV + j*512 + tx*8);
            ulonglong2 v1 = *(ulonglong2*)(sV + j*512 + tx*8 + 4);
            FMA2(acc2[0], ab, v0.x); FMA2(acc2[1], ab, v0.y);
            FMA2(acc2[2], ab, v1.x); FMA2(acc2[3], ab, v1.y);
        }
        float* op = o + vbase + (size_t)i*H_*DV_ + tx*8;
        *(ulonglong2*)op       = make_ulonglong2(acc2[0], acc2[1]);
        *(ulonglong2*)(op + 4) = make_ulonglong2(acc2[2], acc2[3]);
    }
}

// ---------------- retention: inter-chunk scan ----------------
__global__ __launch_bounds__(256) void ret_inter(
    const float* __restrict__ q, const float* __restrict__ k,
    const float* __restrict__ v, float* __restrict__ o)
{
    extern __shared__ float sm[];
    float* S   = sm;
    float* sQt = sm + 16384;
    float* sK  = sm + 32768;
    float* sV  = sm + 49152;
    __shared__ float qdv[64], kdv[64];

    int bx = blockIdx.x;
    int vs = bx & 7; int h = (bx >> 3) & 7; int b = bx >> 6;
    int v0 = vs * 64;
    int tid = threadIdx.x;
    float gamma = 1.f - exp2f(-5.f - (float)h);
    float lg2 = log2f(gamma);
    if (tid < 64) {
        qdv[tid] = 0.0625f * gpow(lg2, (float)(tid + 1));
        kdv[tid] = gpow(lg2, (float)(63 - tid));
    }
    float gC = gpow(lg2, 64.f);
    u64 gC2 = bcast2(gC);
#pragma unroll
    for (int r = 0; r < 64; r++) S[tid + 256*r] = 0.f;
    __syncthreads();

    for (int n = 0; n < NCH; n++) {
        const size_t qbase = ((size_t)(b*T_ + n*C_)*H_ + h)*DK_;
        const size_t vbase = ((size_t)(b*T_ + n*C_)*H_ + h)*DV_ + v0;
#pragma unroll
        for (int r = 0; r < 16; r++) {
            int idx = tid + 256*r;
            int row = idx >> 6;
            int d4  = (idx & 63) << 2;
            float4 qv = *(const float4*)(q + qbase + (size_t)row*H_*DK_ + d4);
            float qs = qdv[row];
            sQt[(d4+0)*64 + row] = qv.x*qs;
            sQt[(d4+1)*64 + row] = qv.y*qs;
            sQt[(d4+2)*64 + row] = qv.z*qs;
            sQt[(d4+3)*64 + row] = qv.w*qs;
            float4 kv = *(const float4*)(k + qbase + (size_t)row*H_*DK_ + d4);
            float ks = kdv[row];
            *(float4*)(sK + row*256 + d4) =
                make_float4(kv.x*ks, kv.y*ks, kv.z*ks, kv.w*ks);
        }
#pragma unroll
        for (int r = 0; r < 4; r++) {
            int idx = tid + 256*r;
            int row = idx >> 4;
            int v4  = (idx & 15) << 2;
            *(float4*)(sV + row*64 + v4) =
                *(const float4*)(v + vbase + (size_t)row*H_*DV_ + v4);
        }
        __syncthreads();

        if (n > 0) {    // o_inter = (Q*qd) @ S
            int ti = tid >> 4, tv = tid & 15;
            int i0 = ti*4, w0 = tv*4;
            u64 acc2[4][2] = {};
            for (int d = 0; d < 256; d++) {
                float4 qa = *(float4*)(sQt + d*64 + i0);
                ulonglong2 sa = *(ulonglong2*)(S + d*64 + w0);
                u64 q0 = bcast2(qa.x), q1 = bcast2(qa.y), q2 = bcast2(qa.z), q3 = bcast2(qa.w);
                FMA2(acc2[0][0], q0, sa.x); FMA2(acc2[0][1], q0, sa.y);
                FMA2(acc2[1][0], q1, sa.x); FMA2(acc2[1][1], q1, sa.y);
                FMA2(acc2[2][0], q2, sa.x); FMA2(acc2[2][1], q2, sa.y);
                FMA2(acc2[3][0], q3, sa.x); FMA2(acc2[3][1], q3, sa.y);
            }
#pragma unroll
            for (int a = 0; a < 4; a++) {
                float f[4];
                unpack2(acc2[a][0], f[0], f[1]);
                unpack2(acc2[a][1], f[2], f[3]);
                float* op = o + ((size_t)(b*T_ + n*C_ + i0 + a)*H_ + h)*DV_ + v0 + w0;
                float4 cur = *(float4*)op;
                cur.x += f[0]; cur.y += f[1]; cur.z += f[2]; cur.w += f[3];
                *(float4*)op = cur;
            }
        }
        __syncthreads();   // all S reads done before update

        {   // S = gC*S + (K*kd)^T @ V
            int td = tid >> 3, tw = tid & 7;
            int d0 = td*8, w0 = tw*8;
            u64 acc2[8][4] = {};
            for (int j = 0; j < 64; j++) {
                float ka[8];
                *(float4*)&ka[0] = *(float4*)(sK + j*256 + d0);
                *(float4*)&ka[4] = *(float4*)(sK + j*256 + d0 + 4);
                ulonglong2 va0 = *(ulonglong2*)(sV + j*64 + w0);
                ulonglong2 va1 = *(ulonglong2*)(sV + j*64 + w0 + 4);
#pragma unroll
                for (int a = 0; a < 8; a++) {
                    u64 kb = bcast2(ka[a]);
                    FMA2(acc2[a][0], kb, va0.x);
                    FMA2(acc2[a][1], kb, va0.y);
                    FMA2(acc2[a][2], kb, va1.x);
                    FMA2(acc2[a][3], kb, va1.y);
                }
            }
#pragma unroll
            for (int a = 0; a < 8; a++)
#pragma unroll
                for (int c2 = 0; c2 < 4; c2++) {
                    u64* sp = (u64*)(S + (d0+a)*64 + w0 + c2*2);
                    u64 sv = *sp;
                    FMA2(acc2[a][c2], gC2, sv);   // acc = gC*S + acc
                    *sp = acc2[a][c2];
                }
        }
        __syncthreads();
    }
}

// ---------------- RMSNorm + swish gate -> fp16 ----------------
__global__ __launch_bounds__(128) void norm_gate(
    const float* __restrict__ o, const float* __restrict__ g, const float* __restrict__ w,
    __half* __restrict__ oh)
{
    int row = blockIdx.x;
    size_t base = (size_t)row * DV_;
    int tid = threadIdx.x;
    float x[4];
    *(float4*)x = *(const float4*)(o + base + tid*4);
    float ss = x[0]*x[0] + x[1]*x[1] + x[2]*x[2] + x[3]*x[3];
#pragma unroll
    for (int off = 16; off; off >>= 1) ss += __shfl_xor_sync(0xffffffffu, ss, off);
    __shared__ float ws[4];
    if ((tid & 31) == 0) ws[tid >> 5] = ss;
    __syncthreads();
    float tot = ws[0] + ws[1] + ws[2] + ws[3];
    float scale = rsqrtf(tot * (1.f/512.f) + 1e-5f);
    float gv[4], wv[4];
    *(float4*)gv = *(const float4*)(g + base + tid*4);
    *(float4*)wv = *(const float4*)(w + tid*4);
    __half2 r01, r23;
    {
        float r0 = x[0]*scale*wv[0]*(gv[0]/(1.f+expf(-gv[0])));
        float r1 = x[1]*scale*wv[1]*(gv[1]/(1.f+expf(-gv[1])));
        float r2 = x[2]*scale*wv[2]*(gv[2]/(1.f+expf(-gv[2])));
        float r3 = x[3]*scale*wv[3]*(gv[3]/(1.f+expf(-gv[3])));
        r01 = __floats2half2_rn(r0, r1);
        r23 = __floats2half2_rn(r2, r3);
    }
    *(uint2*)(oh + base + tid*4) = make_uint2(*(uint32_t*)&r01, *(uint32_t*)&r23);
}

// ---------------- launch ----------------
extern "C" void kernel_launch(void* const* d_in, const int* in_sizes, int n_in,
                              void* d_out, int out_size)
{
    const float* hs = (const float*)d_in[0];
    const float* Wq = (const float*)d_in[1];
    const float* Wk = (const float*)d_in[2];
    const float* Wv = (const float*)d_in[3];
    const float* Wg = (const float*)d_in[4];
    const float* Wo = (const float*)d_in[5];
    const float* gw = (const float*)d_in[6];
    float* out = (float*)d_out;

    float *q, *k, *v, *g, *o, *rc, *rs;
    cudaGetSymbolAddress((void**)&q,  g_q);
    cudaGetSymbolAddress((void**)&k,  g_k);
    cudaGetSymbolAddress((void**)&v,  g_v);
    cudaGetSymbolAddress((void**)&g,  g_g);
    cudaGetSymbolAddress((void**)&o,  g_o);
    cudaGetSymbolAddress((void**)&rc, g_rc);
    cudaGetSymbolAddress((void**)&rs, g_rs);

    __half *hsh, *wq, *wk, *wv, *wg, *wo, *oh;
    cudaGetSymbolAddress((void**)&hsh, g_hsh);
    cudaGetSymbolAddress((void**)&wq, g_wq);
    cudaGetSymbolAddress((void**)&wk, g_wk);
    cudaGetSymbolAddress((void**)&wv, g_wv);
    cudaGetSymbolAddress((void**)&wg, g_wg);
    cudaGetSymbolAddress((void**)&wo, g_wo);
    cudaGetSymbolAddress((void**)&oh, g_oh);

    cudaFuncSetAttribute(ret_intra, cudaFuncAttributeMaxDynamicSharedMemorySize, 147456);
    cudaFuncSetAttribute(ret_inter, cudaFuncAttributeMaxDynamicSharedMemorySize, 212992);
    cudaFuncSetAttribute(gemm_mma,  cudaFuncAttributeMaxDynamicSharedMemorySize, GEMM_SMEM);

    dim3 tb(32, 8);
    // positions 1-3: conversions; positions 4-5: GEMMs (ncu capture window)
    conv_f16<<<(MR*2048/4 + 255)/256, 256>>>(hs, hsh, MR*2048/4);
    tconv<<<dim3(64, 64),  tb>>>(Wq, wq, 2048, 2048);
    tconv<<<dim3(64, 64),  tb>>>(Wk, wk, 2048, 2048);

    gemm_mma<<<dim3(16, 32), 256, GEMM_SMEM>>>(hsh, wq, q, MR, 2048, 2048);
    gemm_mma<<<dim3(16, 32), 256, GEMM_SMEM>>>(hsh, wk, k, MR, 2048, 2048);

    tconv<<<dim3(128, 64), tb>>>(Wv, wv, 2048, 4096);
    gemm_mma<<<dim3(32, 32), 256, GEMM_SMEM>>>(hsh, wv, v, MR, 4096, 2048);
    tconv<<<dim3(128, 64), tb>>>(Wg, wg, 2048, 4096);
    gemm_mma<<<dim3(32, 32), 256, GEMM_SMEM>>>(hsh, wg, g, MR, 4096, 2048);
    tconv<<<dim3(64, 128), tb>>>(Wo, wo, 4096, 2048);

    rope_table<<<1024, 256>>>(rc, rs);
    rope_apply<<<(B_*T_*H_*128)/256, 256>>>(q, k, rc, rs);

    ret_intra<<<B_*H_*NCH, 256, 147456>>>(q, k, v, o);
    ret_inter<<<B_*H_*8,   256, 212992>>>(q, k, v, o);

    norm_gate<<<MR*H_, 128>>>(o, g, gw, oh);

    gemm_mma<<<dim3(16, 32), 256, GEMM_SMEM>>>(oh, wo, out, MR, 2048, 4096);
}

// round 15
// speedup vs baseline: 2.0250x; 1.0435x over previous
#include <cuda_runtime.h>
#include <cuda_fp16.h>
#include <math.h>
#include <stdint.h>

#define B_   2
#define T_   2048
#define H_   8
#define DK_  256
#define DV_  512
#define C_   64
#define NCH  32            // T_/C_
#define MR   (B_*T_)       // 4096 rows

typedef unsigned long long u64;

// ---------------- scratch (no allocations allowed) ----------------
__device__ float g_q[(size_t)MR*H_*DK_];   // [b,t,h,dk]
__device__ float g_k[(size_t)MR*H_*DK_];
__device__ float g_v[(size_t)MR*H_*DV_];   // [b,t,h,dv]
__device__ float g_g[(size_t)MR*H_*DV_];
__device__ float g_o[(size_t)MR*H_*DV_];
__device__ float g_rc[T_*128];
__device__ float g_rs[T_*128];

// fp16 operand buffers
__device__ __half g_hsh[(size_t)MR*2048];
__device__ __half g_wq[(size_t)2048*2048];
__device__ __half g_wk[(size_t)2048*2048];
__device__ __half g_wv[(size_t)4096*2048];
__device__ __half g_wg[(size_t)4096*2048];
__device__ __half g_wo[(size_t)2048*4096];
__device__ __half g_oh[(size_t)MR*4096];

// ================= PTX helpers =================
__device__ __forceinline__ uint32_t smem_u32(const void* p) {
    uint32_t a;
    asm("{ .reg .u64 t; cvta.to.shared.u64 t, %1; cvt.u32.u64 %0, t; }" : "=r"(a) : "l"(p));
    return a;
}
__device__ __forceinline__ void cpa16(uint32_t s, const void* g) {
    asm volatile("cp.async.cg.shared.global [%0], [%1], 16;" :: "r"(s), "l"(g));
}
__device__ __forceinline__ void cp_commit() {
    asm volatile("cp.async.commit_group;" ::: "memory");
}
__device__ __forceinline__ void cp_wait2() {
    asm volatile("cp.async.wait_group 2;" ::: "memory");
}
__device__ __forceinline__ void ldm4(uint32_t* r, uint32_t a) {
    asm volatile("ldmatrix.sync.aligned.m8n8.x4.shared.b16 {%0,%1,%2,%3}, [%4];"
        : "=r"(r[0]), "=r"(r[1]), "=r"(r[2]), "=r"(r[3]) : "r"(a));
}
__device__ __forceinline__ void mma16816(float* c, const uint32_t* a, const uint32_t* b) {
    asm volatile(
        "mma.sync.aligned.m16n8k16.row.col.f32.f16.f16.f32 "
        "{%0,%1,%2,%3}, {%4,%5,%6,%7}, {%8,%9}, {%0,%1,%2,%3};"
        : "+f"(c[0]), "+f"(c[1]), "+f"(c[2]), "+f"(c[3])
        : "r"(a[0]), "r"(a[1]), "r"(a[2]), "r"(a[3]), "r"(b[0]), "r"(b[1]));
}
// packed f32x2
__device__ __forceinline__ u64 pack2(float x, float y) {
    u64 r; asm("mov.b64 %0, {%1, %2};" : "=l"(r) : "f"(x), "f"(y)); return r;
}
__device__ __forceinline__ u64 bcast2(float x) { return pack2(x, x); }
#define FMA2(d, a, b) asm("fma.rn.f32x2 %0, %1, %2, %0;" : "+l"(d) : "l"(a), "l"(b))
__device__ __forceinline__ void unpack2(u64 v, float& lo, float& hi) {
    asm("mov.b64 {%0, %1}, %2;" : "=f"(lo), "=f"(hi) : "l"(v));
}
__device__ __forceinline__ float gpow(float lg2, float e) {
    return exp2f(e * lg2);
}

// ================= conversion kernels =================
__global__ void conv_f16(const float* __restrict__ x, __half* __restrict__ h, int n4)
{
    int i = blockIdx.x * 256 + threadIdx.x;
    if (i >= n4) return;
    float4 v = *(const float4*)(x + (size_t)i * 4);
    __half2 a = __floats2half2_rn(v.x, v.y);
    __half2 b = __floats2half2_rn(v.z, v.w);
    *(uint2*)(h + (size_t)i*4) = make_uint2(
        *(uint32_t*)&a, *(uint32_t*)&b);
}

// W[K,N] -> Wt fp16 [N,K]
__global__ void tconv(const float* __restrict__ W, __half* __restrict__ h, int K, int N)
{
    __shared__ float tile[32][33];
    int k0 = blockIdx.y * 32, n0 = blockIdx.x * 32;
    int tx = threadIdx.x, ty = threadIdx.y;
#pragma unroll
    for (int i = 0; i < 4; i++)
        tile[ty + 8*i][tx] = W[(size_t)(k0 + ty + 8*i) * N + n0 + tx];
    __syncthreads();
#pragma unroll
    for (int i = 0; i < 4; i++)
        h[(size_t)(n0 + ty + 8*i) * K + k0 + tx] = __float2half(tile[tx][ty + 8*i]);
}

// ================= HMMA GEMM body: C[:,n0..][M,K] = A @ Bt^T =================
// fp16 operands, fp32 accum. CTA tile 128x128, BK=32, 4-stage cp.async,
// single barrier per chunk. 20KB/stage, 80KB total -> 2 CTAs per SM.
#define OAH 0u
#define OBH 10240u
#define SSTG 20480u
#define GEMM_SMEM (4*20480)

__device__ __forceinline__ void gemm_body(
    const __half* __restrict__ Ah, const __half* __restrict__ Bt,
    float* __restrict__ Cc, int N, int K, int m0, int n0,
    uint32_t sb, int tid)
{
    const int lane = tid & 31, w = tid >> 5;
    const int wm = w & 3, wn = w >> 2;
    const int NC = K >> 5;

    float c[2][8][4] = {};

    auto load_stage = [&](int s, int k0) {
        uint32_t base = sb + (uint32_t)s * SSTG;
#pragma unroll
        for (int i = 0; i < 2; i++) {
            int idx = tid + (i << 8);
            int r = idx >> 2, kc = idx & 3;
            uint32_t da = base + r * 80 + kc * 16;
            cpa16(da + OAH, Ah + (size_t)(m0 + r) * K + k0 + kc * 8);
            cpa16(da + OBH, Bt + (size_t)(n0 + r) * K + k0 + kc * 8);
        }
    };

    load_stage(0, 0);  cp_commit();
    load_stage(1, 32); cp_commit();
    load_stage(2, 64); cp_commit();

    for (int i = 0; i < NC; i++) {
        cp_wait2();
        __syncthreads();   // single barrier: orders prior-iter reads before overwrite
        if (i + 3 < NC) load_stage((i + 3) & 3, (i + 3) << 5);
        cp_commit();

        uint32_t base = sb + (uint32_t)(i & 3) * SSTG;
#pragma unroll
        for (int ks = 0; ks < 2; ks++) {
            uint32_t ah[2][4];
#pragma unroll
            for (int mt = 0; mt < 2; mt++) {
                int row = wm * 32 + mt * 16 + (lane & 15);
                int kc = ks * 2 + (lane >> 4);
                ldm4(ah[mt], base + OAH + row * 80 + kc * 16);
            }
            uint32_t bh[4][4];
#pragma unroll
            for (int np = 0; np < 4; np++) {
                int row = wn * 64 + np * 16 + (lane & 7) + ((lane & 16) >> 1);
                int kc = ks * 2 + ((lane >> 3) & 1);
                ldm4(bh[np], base + OBH + row * 80 + kc * 16);
            }
#pragma unroll
            for (int mt = 0; mt < 2; mt++)
#pragma unroll
                for (int np = 0; np < 4; np++)
#pragma unroll
                    for (int hf = 0; hf < 2; hf++)
                        mma16816(c[mt][np * 2 + hf], ah[mt], &bh[np][hf * 2]);
        }
    }

    const int rbase = m0 + wm * 32 + (lane >> 2);
    const int cbase = n0 + wn * 64 + (lane & 3) * 2;
#pragma unroll
    for (int mt = 0; mt < 2; mt++)
#pragma unroll
        for (int nt = 0; nt < 8; nt++) {
            *(float2*)&Cc[(size_t)(rbase + mt * 16) * N + cbase + nt * 8] =
                make_float2(c[mt][nt][0], c[mt][nt][1]);
            *(float2*)&Cc[(size_t)(rbase + mt * 16 + 8) * N + cbase + nt * 8] =
                make_float2(c[mt][nt][2], c[mt][nt][3]);
        }
}

// fused Q/K/V/G projection: blockIdx.x in [0,96) selects weight/output
__global__ __launch_bounds__(256, 2) void gemm_proj(
    const __half* __restrict__ A,
    const __half* __restrict__ wq, const __half* __restrict__ wk,
    const __half* __restrict__ wv, const __half* __restrict__ wg,
    float* __restrict__ q, float* __restrict__ k,
    float* __restrict__ v, float* __restrict__ g)
{
    extern __shared__ __align__(128) char smc[];
    uint32_t sb = smem_u32(smc);
    int nt = blockIdx.x;
    const __half* Bt; float* Cc; int N, nb;
    if (nt < 16)      { Bt = wq; Cc = q; N = 2048; nb = nt; }
    else if (nt < 32) { Bt = wk; Cc = k; N = 2048; nb = nt - 16; }
    else if (nt < 64) { Bt = wv; Cc = v; N = 4096; nb = nt - 32; }
    else              { Bt = wg; Cc = g; N = 4096; nb = nt - 64; }
    gemm_body(A, Bt, Cc, N, 2048, blockIdx.y * 128, nb * 128, sb, threadIdx.x);
}

__global__ __launch_bounds__(256, 2) void gemm_mma(
    const __half* __restrict__ Ah, const __half* __restrict__ Bt,
    float* __restrict__ Cc, int M, int N, int K)
{
    extern __shared__ __align__(128) char smc[];
    gemm_body(Ah, Bt, Cc, N, K, blockIdx.y * 128, blockIdx.x * 128,
              smem_u32(smc), threadIdx.x);
}

// ---------------- rotary (fp32, mirrors the reference's own f32 math) --------
__global__ void rope_table(float* __restrict__ rc, float* __restrict__ rs)
{
    int idx = blockIdx.x * blockDim.x + threadIdx.x;   // t*128 + j
    if (idx >= T_*128) return;
    int t = idx >> 7, j = idx & 127;
    float inv = 1.0f / powf(10000.0f, (float)j * (1.0f/128.0f));
    float a = (float)t * inv;
    float s, c;
    sincosf(a, &s, &c);
    rc[idx] = c;
    rs[idx] = s;
}

__global__ void rope_apply(float* __restrict__ q, float* __restrict__ k,
                           const float* __restrict__ rc, const float* __restrict__ rs)
{
    int idx = blockIdx.x * blockDim.x + threadIdx.x;
    if (idx >= B_*T_*H_*128) return;
    int j = idx & 127;
    int h = (idx >> 7) & (H_-1);
    int t = (idx >> 10) & (T_-1);
    int b = idx >> 21;
    float c = rc[t*128 + j], s = rs[t*128 + j];
    size_t base = ((size_t)(b*T_ + t)*H_ + h)*DK_;
    float x1 = q[base + j], x2 = q[base + 128 + j];
    q[base + j]       = x1*c - x2*s;
    q[base + 128 + j] = x2*c + x1*s;
    x1 = k[base + j]; x2 = k[base + 128 + j];
    k[base + j]       = x1*c - x2*s;
    k[base + 128 + j] = x2*c + x1*s;
}

// ---------------- retention: intra-chunk (fully parallel) ----------------
__global__ __launch_bounds__(256) void ret_intra(
    const float* __restrict__ q, const float* __restrict__ k,
    const float* __restrict__ v, float* __restrict__ o)
{
    extern __shared__ float sm[];
    float* sQt = sm;              // [256][64]
    float* sKt = sm + 16384;      // [256][64]
    float* sA  = sm + 32768;      // [64][64]
    float* sV  = sm;              // reuse [64][512]
    __shared__ float gp[64];

    int bx = blockIdx.x;
    int n = bx % NCH; int h = (bx / NCH) % H_; int b = bx / (NCH*H_);
    int tid = threadIdx.x;
    float gamma = 1.f - exp2f(-5.f - (float)h);
    float lg2 = log2f(gamma);
    if (tid < 64) gp[tid] = gpow(lg2, (float)tid);

    const size_t qbase = ((size_t)(b*T_ + n*C_)*H_ + h)*DK_;
#pragma unroll
    for (int r = 0; r < 16; r++) {
        int idx = tid + 256*r;
        int row = idx >> 6;
        int d4  = (idx & 63) << 2;
        float4 qv = *(const float4*)(q + qbase + (size_t)row*H_*DK_ + d4);
        sQt[(d4+0)*64 + row] = qv.x * 0.0625f;
        sQt[(d4+1)*64 + row] = qv.y * 0.0625f;
        sQt[(d4+2)*64 + row] = qv.z * 0.0625f;
        sQt[(d4+3)*64 + row] = qv.w * 0.0625f;
        float4 kv = *(const float4*)(k + qbase + (size_t)row*H_*DK_ + d4);
        sKt[(d4+0)*64 + row] = kv.x;
        sKt[(d4+1)*64 + row] = kv.y;
        sKt[(d4+2)*64 + row] = kv.z;
        sKt[(d4+3)*64 + row] = kv.w;
    }
    __syncthreads();
    {
        int ti = tid >> 4, tj = tid & 15;
        u64 acc2[4][2] = {};
        for (int d = 0; d < 256; d++) {
            float4 qa = *(float4*)(sQt + d*64 + ti*4);
            ulonglong2 ka = *(ulonglong2*)(sKt + d*64 + tj*4);
            u64 q0 = bcast2(qa.x), q1 = bcast2(qa.y), q2 = bcast2(qa.z), q3 = bcast2(qa.w);
            FMA2(acc2[0][0], q0, ka.x); FMA2(acc2[0][1], q0, ka.y);
            FMA2(acc2[1][0], q1, ka.x); FMA2(acc2[1][1], q1, ka.y);
            FMA2(acc2[2][0], q2, ka.x); FMA2(acc2[2][1], q2, ka.y);
            FMA2(acc2[3][0], q3, ka.x); FMA2(acc2[3][1], q3, ka.y);
        }
#pragma unroll
        for (int a = 0; a < 4; a++) {
            float f[4];
            unpack2(acc2[a][0], f[0], f[1]);
            unpack2(acc2[a][1], f[2], f[3]);
#pragma unroll
            for (int c = 0; c < 4; c++) {
                int i = ti*4 + a, j = tj*4 + c;
                sA[i*64 + j] = (i >= j) ? f[c] * gp[i-j] : 0.f;
            }
        }
    }
    __syncthreads();
    const size_t vbase = ((size_t)(b*T_ + n*C_)*H_ + h)*DV_;
#pragma unroll
    for (int r = 0; r < 32; r++) {
        int idx = tid + 256*r;
        int row = idx >> 7;
        int v4  = (idx & 127) << 2;
        *(float4*)(sV + row*512 + v4) =
            *(const float4*)(v + vbase + (size_t)row*H_*DV_ + v4);
    }
    __syncthreads();
    int ty = tid >> 6;
    int tx = tid & 63;
    for (int ii = 0; ii < 16; ii++) {
        int i = ty*16 + ii;
        u64 acc2[4] = {};
        for (int j = 0; j < 64; j++) {
            u64 ab = bcast2(sA[i*64 + j]);
            ulonglong2 v0 = *(ulonglong2*)(sV + j*512 + tx*8);
            ulonglong2 v1 = *(ulonglong2*)(sV + j*512 + tx*8 + 4);
            FMA2(acc2[0], ab, v0.x); FMA2(acc2[1], ab, v0.y);
            FMA2(acc2[2], ab, v1.x); FMA2(acc2[3], ab, v1.y);
        }
        float* op = o + vbase + (size_t)i*H_*DV_ + tx*8;
        *(ulonglong2*)op       = make_ulonglong2(acc2[0], acc2[1]);
        *(ulonglong2*)(op + 4) = make_ulonglong2(acc2[2], acc2[3]);
    }
}

// ---------------- retention: inter-chunk scan ----------------
__global__ __launch_bounds__(256) void ret_inter(
    const float* __restrict__ q, const float* __restrict__ k,
    const float* __restrict__ v, float* __restrict__ o)
{
    extern __shared__ float sm[];
    float* S   = sm;
    float* sQt = sm + 16384;
    float* sK  = sm + 32768;
    float* sV  = sm + 49152;
    __shared__ float qdv[64], kdv[64];

    int bx = blockIdx.x;
    int vs = bx & 7; int h = (bx >> 3) & 7; int b = bx >> 6;
    int v0 = vs * 64;
    int tid = threadIdx.x;
    float gamma = 1.f - exp2f(-5.f - (float)h);
    float lg2 = log2f(gamma);
    if (tid < 64) {
        qdv[tid] = 0.0625f * gpow(lg2, (float)(tid + 1));
        kdv[tid] = gpow(lg2, (float)(63 - tid));
    }
    float gC = gpow(lg2, 64.f);
    u64 gC2 = bcast2(gC);
#pragma unroll
    for (int r = 0; r < 64; r++) S[tid + 256*r] = 0.f;
    __syncthreads();

    for (int n = 0; n < NCH; n++) {
        const size_t qbase = ((size_t)(b*T_ + n*C_)*H_ + h)*DK_;
        const size_t vbase = ((size_t)(b*T_ + n*C_)*H_ + h)*DV_ + v0;
#pragma unroll
        for (int r = 0; r < 16; r++) {
            int idx = tid + 256*r;
            int row = idx >> 6;
            int d4  = (idx & 63) << 2;
            float4 qv = *(const float4*)(q + qbase + (size_t)row*H_*DK_ + d4);
            float qs = qdv[row];
            sQt[(d4+0)*64 + row] = qv.x*qs;
            sQt[(d4+1)*64 + row] = qv.y*qs;
            sQt[(d4+2)*64 + row] = qv.z*qs;
            sQt[(d4+3)*64 + row] = qv.w*qs;
            float4 kv = *(const float4*)(k + qbase + (size_t)row*H_*DK_ + d4);
            float ks = kdv[row];
            *(float4*)(sK + row*256 + d4) =
                make_float4(kv.x*ks, kv.y*ks, kv.z*ks, kv.w*ks);
        }
#pragma unroll
        for (int r = 0; r < 4; r++) {
            int idx = tid + 256*r;
            int row = idx >> 4;
            int v4  = (idx & 15) << 2;
            *(float4*)(sV + row*64 + v4) =
                *(const float4*)(v + vbase + (size_t)row*H_*DV_ + v4);
        }
        __syncthreads();

        if (n > 0) {    // o_inter = (Q*qd) @ S
            int ti = tid >> 4, tv = tid & 15;
            int i0 = ti*4, w0 = tv*4;
            u64 acc2[4][2] = {};
            for (int d = 0; d < 256; d++) {
                float4 qa = *(float4*)(sQt + d*64 + i0);
                ulonglong2 sa = *(ulonglong2*)(S + d*64 + w0);
                u64 q0 = bcast2(qa.x), q1 = bcast2(qa.y), q2 = bcast2(qa.z), q3 = bcast2(qa.w);
                FMA2(acc2[0][0], q0, sa.x); FMA2(acc2[0][1], q0, sa.y);
                FMA2(acc2[1][0], q1, sa.x); FMA2(acc2[1][1], q1, sa.y);
                FMA2(acc2[2][0], q2, sa.x); FMA2(acc2[2][1], q2, sa.y);
                FMA2(acc2[3][0], q3, sa.x); FMA2(acc2[3][1], q3, sa.y);
            }
#pragma unroll
            for (int a = 0; a < 4; a++) {
                float f[4];
                unpack2(acc2[a][0], f[0], f[1]);
                unpack2(acc2[a][1], f[2], f[3]);
                float* op = o + ((size_t)(b*T_ + n*C_ + i0 + a)*H_ + h)*DV_ + v0 + w0;
                float4 cur = *(float4*)op;
                cur.x += f[0]; cur.y += f[1]; cur.z += f[2]; cur.w += f[3];
                *(float4*)op = cur;
            }
        }
        __syncthreads();   // all S reads done before update

        {   // S = gC*S + (K*kd)^T @ V
            int td = tid >> 3, tw = tid & 7;
            int d0 = td*8, w0 = tw*8;
            u64 acc2[8][4] = {};
            for (int j = 0; j < 64; j++) {
                float ka[8];
                *(float4*)&ka[0] = *(float4*)(sK + j*256 + d0);
                *(float4*)&ka[4] = *(float4*)(sK + j*256 + d0 + 4);
                ulonglong2 va0 = *(ulonglong2*)(sV + j*64 + w0);
                ulonglong2 va1 = *(ulonglong2*)(sV + j*64 + w0 + 4);
#pragma unroll
                for (int a = 0; a < 8; a++) {
                    u64 kb = bcast2(ka[a]);
                    FMA2(acc2[a][0], kb, va0.x);
                    FMA2(acc2[a][1], kb, va0.y);
                    FMA2(acc2[a][2], kb, va1.x);
                    FMA2(acc2[a][3], kb, va1.y);
                }
            }
#pragma unroll
            for (int a = 0; a < 8; a++)
#pragma unroll
                for (int c2 = 0; c2 < 4; c2++) {
                    u64* sp = (u64*)(S + (d0+a)*64 + w0 + c2*2);
                    u64 sv = *sp;
                    FMA2(acc2[a][c2], gC2, sv);   // acc = gC*S + acc
                    *sp = acc2[a][c2];
                }
        }
        __syncthreads();
    }
}

// ---------------- RMSNorm + swish gate -> fp16 ----------------
__global__ __launch_bounds__(128) void norm_gate(
    const float* __restrict__ o, const float* __restrict__ g, const float* __restrict__ w,
    __half* __restrict__ oh)
{
    int row = blockIdx.x;
    size_t base = (size_t)row * DV_;
    int tid = threadIdx.x;
    float x[4];
    *(float4*)x = *(const float4*)(o + base + tid*4);
    float ss = x[0]*x[0] + x[1]*x[1] + x[2]*x[2] + x[3]*x[3];
#pragma unroll
    for (int off = 16; off; off >>= 1) ss += __shfl_xor_sync(0xffffffffu, ss, off);
    __shared__ float ws[4];
    if ((tid & 31) == 0) ws[tid >> 5] = ss;
    __syncthreads();
    float tot = ws[0] + ws[1] + ws[2] + ws[3];
    float scale = rsqrtf(tot * (1.f/512.f) + 1e-5f);
    float gv[4], wv[4];
    *(float4*)gv = *(const float4*)(g + base + tid*4);
    *(float4*)wv = *(const float4*)(w + tid*4);
    __half2 r01, r23;
    {
        float r0 = x[0]*scale*wv[0]*(gv[0]/(1.f+expf(-gv[0])));
        float r1 = x[1]*scale*wv[1]*(gv[1]/(1.f+expf(-gv[1])));
        float r2 = x[2]*scale*wv[2]*(gv[2]/(1.f+expf(-gv[2])));
        float r3 = x[3]*scale*wv[3]*(gv[3]/(1.f+expf(-gv[3])));
        r01 = __floats2half2_rn(r0, r1);
        r23 = __floats2half2_rn(r2, r3);
    }
    *(uint2*)(oh + base + tid*4) = make_uint2(*(uint32_t*)&r01, *(uint32_t*)&r23);
}

// ---------------- launch ----------------
extern "C" void kernel_launch(void* const* d_in, const int* in_sizes, int n_in,
                              void* d_out, int out_size)
{
    const float* hs = (const float*)d_in[0];
    const float* Wq = (const float*)d_in[1];
    const float* Wk = (const float*)d_in[2];
    const float* Wv = (const float*)d_in[3];
    const float* Wg = (const float*)d_in[4];
    const float* Wo = (const float*)d_in[5];
    const float* gw = (const float*)d_in[6];
    float* out = (float*)d_out;

    float *q, *k, *v, *g, *o, *rc, *rs;
    cudaGetSymbolAddress((void**)&q,  g_q);
    cudaGetSymbolAddress((void**)&k,  g_k);
    cudaGetSymbolAddress((void**)&v,  g_v);
    cudaGetSymbolAddress((void**)&g,  g_g);
    cudaGetSymbolAddress((void**)&o,  g_o);
    cudaGetSymbolAddress((void**)&rc, g_rc);
    cudaGetSymbolAddress((void**)&rs, g_rs);

    __half *hsh, *wq, *wk, *wv, *wg, *wo, *oh;
    cudaGetSymbolAddress((void**)&hsh, g_hsh);
    cudaGetSymbolAddress((void**)&wq, g_wq);
    cudaGetSymbolAddress((void**)&wk, g_wk);
    cudaGetSymbolAddress((void**)&wv, g_wv);
    cudaGetSymbolAddress((void**)&wg, g_wg);
    cudaGetSymbolAddress((void**)&wo, g_wo);
    cudaGetSymbolAddress((void**)&oh, g_oh);

    cudaFuncSetAttribute(ret_intra, cudaFuncAttributeMaxDynamicSharedMemorySize, 147456);
    cudaFuncSetAttribute(ret_inter, cudaFuncAttributeMaxDynamicSharedMemorySize, 212992);
    cudaFuncSetAttribute(gemm_mma,  cudaFuncAttributeMaxDynamicSharedMemorySize, GEMM_SMEM);
    cudaFuncSetAttribute(gemm_proj, cudaFuncAttributeMaxDynamicSharedMemorySize, GEMM_SMEM);

    dim3 tb(32, 8);
    // positions 1-5: conversions; position 6: fused projection GEMM (ncu -s 5)
    conv_f16<<<(MR*2048/4 + 255)/256, 256>>>(hs, hsh, MR*2048/4);
    tconv<<<dim3(64, 64),  tb>>>(Wq, wq, 2048, 2048);
    tconv<<<dim3(64, 64),  tb>>>(Wk, wk, 2048, 2048);
    tconv<<<dim3(128, 64), tb>>>(Wv, wv, 2048, 4096);
    tconv<<<dim3(128, 64), tb>>>(Wg, wg, 2048, 4096);

    gemm_proj<<<dim3(96, 32), 256, GEMM_SMEM>>>(hsh, wq, wk, wv, wg, q, k, v, g);

    tconv<<<dim3(64, 128), tb>>>(Wo, wo, 4096, 2048);
    rope_table<<<1024, 256>>>(rc, rs);
    rope_apply<<<(B_*T_*H_*128)/256, 256>>>(q, k, rc, rs);

    ret_intra<<<B_*H_*NCH, 256, 147456>>>(q, k, v, o);
    ret_inter<<<B_*H_*8,   256, 212992>>>(q, k, v, o);

    norm_gate<<<MR*H_, 128>>>(o, g, gw, oh);

    gemm_mma<<<dim3(16, 32), 256, GEMM_SMEM>>>(oh, wo, out, MR, 2048, 4096);
}